// round 4
// baseline (speedup 1.0000x reference)
#include <cuda_runtime.h>
#include <cstdint>
#include <cstddef>

// ---------------- problem constants ----------------
#define SQ   32      // sequences
#define PP64 64      // peds per sequence
#define NB   2048    // SQ*PP64
#define PPRW 4096    // PP64*PP64 rows per sequence
#define D1   512
#define D2   1024
#define NKAP 16      // grouped-k: kappa = (e&1)*8 + t
#define EPSV 1e-5f

// ---------------- scratch (static device arrays; no allocation) ----------------
__device__ __align__(256) float g_a  [NB * 512];          // obs @ W_sp           (4 MB)
__device__ __align__(256) float g_hW [NB * 512];          // h @ W1[512:576]      (4 MB)
__device__ __align__(256) float g_U  [NB * NKAP * 512];   // grouped a@W1         (64 MB)
__device__ __align__(256) float g_V  [NKAP * 512];        // grouped b_sp@W1
__device__ __align__(256) float g_Z1 [(size_t)NB * PP64 * 512];  // pre-BN1       (256 MB)
__device__ float  g_sum1[SQ * 512];
__device__ float  g_sq1 [SQ * 512];
__device__ float2 g_ab1 [SQ * 512];
__device__ float  g_sum2[SQ * D2];
__device__ float  g_sq2 [SQ * D2];
__device__ float2 g_ab2 [SQ * D2];
__device__ __align__(256) float g_maxZ[NB * D2];          // per (s,i,d) max_j Z2 (8 MB)
__device__ __align__(256) float g_minZ[NB * D2];          // per (s,i,d) min_j Z2 (8 MB)

// ---------------- f32x2 packed-FMA helpers (sm_100+) ----------------
#define PACKX2(out, f) \
    asm("mov.b64 %0, {%1, %1};" : "=l"(out) : "r"(__float_as_uint(f)))
#define FMAX2(c, a, b) \
    asm("fma.rn.f32x2 %0, %1, %2, %0;" : "+l"(c) : "l"(a), "l"(b))
#define UNPACKX2(lo, hi, v) \
    asm("mov.b64 {%0, %1}, %2;" : "=r"(lo), "=r"(hi) : "l"(v))

// ---------------- K0: zero BN accumulators ----------------
__global__ void k_zero() {
    int i = blockIdx.x * blockDim.x + threadIdx.x;
    if (i < SQ * 512) { g_sum1[i] = 0.f; g_sq1[i] = 0.f; }
    if (i < SQ * D2)  { g_sum2[i] = 0.f; g_sq2[i] = 0.f; }
}

// ---------------- K1: a = obs @ W_sp ; hW = h @ W1[512:576,:] ----------------
__global__ void k_embed(const float* __restrict__ traj, const float* __restrict__ Wsp,
                        const float* __restrict__ hs,   const float* __restrict__ W1) {
    int b = blockIdx.x;            // 0..2047
    int tid = threadIdx.x;         // 128
    __shared__ float obs[16];
    __shared__ float hsh[64];
    if (tid < 16) {
        int t = tid >> 1, c = tid & 1;
        obs[tid] = traj[((size_t)t * NB + b) * 2 + c];   // feature idx = t*2+c
    }
    if (tid < 64) hsh[tid] = hs[b * 64 + tid];
    __syncthreads();
#pragma unroll
    for (int q = 0; q < 4; q++) {
        int f = tid + 128 * q;
        float acc = 0.f;
#pragma unroll
        for (int r = 0; r < 16; r++) acc = fmaf(obs[r], Wsp[r * 512 + f], acc);
        g_a[b * 512 + f] = acc;
        float ah = 0.f;
#pragma unroll
        for (int k = 0; k < 64; k++) ah = fmaf(hsh[k], W1[(512 + k) * 512 + f], ah);
        g_hW[b * 512 + f] = ah;
    }
}

// ---------------- K1b: V[kap][d] = sum_{f in group kap} b_sp[f]*W1[f][d] ----------------
__global__ void k_V(const float* __restrict__ bsp, const float* __restrict__ W1) {
    int d = blockIdx.x * 128 + threadIdx.x;   // grid 4 x 128 -> 512
#pragma unroll
    for (int kap = 0; kap < NKAP; kap++) {
        int par = kap >> 3, t = kap & 7;
        float acc = 0.f;
#pragma unroll 4
        for (int e = par; e < 64; e += 2) {
            int f = t * 64 + e;
            acc = fmaf(bsp[f], W1[f * 512 + d], acc);
        }
        g_V[kap * 512 + d] = acc;
    }
}

// ---------------- K2: U[b][kap][d] = sum_{f in group kap} a[b][f]*W1[f][d] ----------------
// grid 256 blocks x 512 threads; 8 peds per block share W1 reads.
__global__ void k_U(const float* __restrict__ W1) {
    int b0 = blockIdx.x * 8;
    int d  = threadIdx.x;           // 0..511
    __shared__ float a[8][512];
    for (int idx = threadIdx.x; idx < 8 * 512; idx += 512)
        a[idx >> 9][idx & 511] = g_a[b0 * 512 + idx];
    __syncthreads();
#pragma unroll 1
    for (int kap = 0; kap < NKAP; kap++) {
        int par = kap >> 3, t = kap & 7;
        float acc[8];
#pragma unroll
        for (int bb = 0; bb < 8; bb++) acc[bb] = 0.f;
#pragma unroll 4
        for (int e = par; e < 64; e += 2) {
            int f = t * 64 + e;
            float w1 = W1[f * 512 + d];
#pragma unroll
            for (int bb = 0; bb < 8; bb++) acc[bb] = fmaf(a[bb][f], w1, acc[bb]);
        }
#pragma unroll
        for (int bb = 0; bb < 8; bb++)
            g_U[(size_t)((b0 + bb) * NKAP + kap) * 512 + d] = acc[bb];
    }
}

// ---------------- K3a: Z1[(i,j)][d] = hW_j[d] + sum_kap w[ij,kap]*U_j[kap][d] ----------------
// grid (dtile=4, j=64, s=32), 128 threads (one d each). U_j hoisted to regs.
__global__ void k_p1(const float* __restrict__ tw) {
    int tid = threadIdx.x;
    int dt = blockIdx.x, j = blockIdx.y, s = blockIdx.z;
    int d  = (dt << 7) + tid;
    int bj = (s << 6) + j;
    __shared__ float wsh[64][16];
    for (int idx = tid; idx < 1024; idx += 128) {
        int i = idx >> 4, kap = idx & 15;
        wsh[i][kap] = tw[(size_t)((s << 12) + (i << 6) + j) * 16 + kap];
    }
    float uj[16];
#pragma unroll
    for (int kap = 0; kap < 16; kap++)
        uj[kap] = g_U[(size_t)((bj << 4) + kap) * 512 + d];
    float hwj = g_hW[bj * 512 + d];
    __syncthreads();
    float* zbase = g_Z1 + (size_t)((s << 12) + j) * 512 + d;
#pragma unroll 4
    for (int i = 0; i < 64; i++) {
        float acc = hwj;
#pragma unroll
        for (int kap = 0; kap < 16; kap++) acc = fmaf(wsh[i][kap], uj[kap], acc);
        zbase[(size_t)i * (64 * 512)] = acc;
    }
}

// ---------------- K3b: Z1 += sum_kap w[ij,kap]*(V - U_i)[kap][d]; BN1 stats ----------------
// grid (dtile=4, i=64, s=32), 128 threads.
__global__ void k_p2(const float* __restrict__ tw) {
    int tid = threadIdx.x;
    int dt = blockIdx.x, i = blockIdx.y, s = blockIdx.z;
    int d  = (dt << 7) + tid;
    int bi = (s << 6) + i;
    __shared__ float wsh[64][16];
    for (int idx = tid; idx < 1024; idx += 128)
        ((float*)wsh)[idx] = tw[(size_t)((s << 12) + (i << 6)) * 16 + idx];
    float vu[16];
#pragma unroll
    for (int kap = 0; kap < 16; kap++)
        vu[kap] = g_V[(kap << 9) + d] - g_U[(size_t)((bi << 4) + kap) * 512 + d];
    __syncthreads();
    float lsum = 0.f, lsq = 0.f;
    float* zbase = g_Z1 + (size_t)((s << 12) + (i << 6)) * 512 + d;
#pragma unroll 4
    for (int j = 0; j < 64; j++) {
        float acc = 0.f;
#pragma unroll
        for (int kap = 0; kap < 16; kap++) acc = fmaf(wsh[j][kap], vu[kap], acc);
        float z = zbase[(size_t)j * 512] + acc;
        zbase[(size_t)j * 512] = z;
        lsum += z;
        lsq  = fmaf(z, z, lsq);
    }
    atomicAdd(&g_sum1[(s << 9) + d], lsum);
    atomicAdd(&g_sq1 [(s << 9) + d], lsq);
}

// ---------------- K4: finalize BN1 scale/shift ----------------
__global__ void k_bn1(const float* __restrict__ g1, const float* __restrict__ be1) {
    int idx = blockIdx.x * 256 + threadIdx.x;       // SQ*512 = 16384
    if (idx >= SQ * 512) return;
    int d = idx & 511;
    const float inv = 1.f / (float)PPRW;
    float m   = g_sum1[idx] * inv;
    float var = g_sq1[idx] * inv - m * m;
    float al  = g1[d] * rsqrtf(var + EPSV);
    g_ab1[idx] = make_float2(al, fmaf(-al, m, be1[d]));
}

// ---------------- K5: GEMM2 (A1 = relu(bn1(Z1)), Z2 = A1@W2) with fused
//                  per-(s,i,d) max/min over j and BN2 partial sums.
// Block: M=64 rows (= one (s,i), all j), N=128 cols, K=512 (BK=16), f32x2 FMA.
__global__ void __launch_bounds__(256, 2) k_gemm2(const float* __restrict__ W2) {
    const int nblk = blockIdx.x;       // 0..7
    const int si   = blockIdx.y;       // 0..2047
    const int s    = si >> 6;
    const int tid  = threadIdx.x;
    const int tx   = tid & 31;         // 32 x TN4 = 128 cols
    const int ty   = tid >> 5;         // 8  x TM8 = 64 rows

    __shared__ __align__(16) float As[2][16][66];   // padded: conflict-free STS, 8B pairs
    __shared__ __align__(16) float Bs[2][16][128];
    __shared__ float2 ab[512];
    __shared__ float rmax[8][128], rmin[8][128], rsum[8][128], rsq[8][128];

    for (int idx = tid; idx < 512; idx += 256) ab[idx] = g_ab1[(s << 9) + idx];
    __syncthreads();

    const int a_row = tid >> 2;          // 0..63
    const int a_k4  = (tid & 3) << 2;    // 0,4,8,12
    const int b_row = tid >> 4;          // 0..15
    const int b_col = (tid & 15) << 3;   // 0..120
    const int n0    = nblk << 7;

    const float* Z1 = g_Z1 + (size_t)si * (64 * 512);

    unsigned long long acc[4][4];
#pragma unroll
    for (int mp = 0; mp < 4; mp++)
#pragma unroll
        for (int nn = 0; nn < 4; nn++) acc[mp][nn] = 0ull;

    float4 av, bv0, bv1;
    av  = *(const float4*)(Z1 + (size_t)a_row * 512 + a_k4);
    bv0 = *(const float4*)(W2 + (size_t)b_row * D2 + n0 + b_col);
    bv1 = *(const float4*)(W2 + (size_t)b_row * D2 + n0 + b_col + 4);
    {
        float va[4] = {av.x, av.y, av.z, av.w};
#pragma unroll
        for (int q = 0; q < 4; q++) {
            float2 al = ab[a_k4 + q];
            As[0][a_k4 + q][a_row] = fmaxf(fmaf(al.x, va[q], al.y), 0.f);
        }
        *(float4*)&Bs[0][b_row][b_col]     = bv0;
        *(float4*)&Bs[0][b_row][b_col + 4] = bv1;
    }
    __syncthreads();

    int buf = 0;
    for (int kt = 0; kt < 32; kt++) {
        const int k0n = (kt + 1) << 4;
        if (kt < 31) {
            av  = *(const float4*)(Z1 + (size_t)a_row * 512 + k0n + a_k4);
            bv0 = *(const float4*)(W2 + (size_t)(k0n + b_row) * D2 + n0 + b_col);
            bv1 = *(const float4*)(W2 + (size_t)(k0n + b_row) * D2 + n0 + b_col + 4);
        }
#pragma unroll
        for (int kk = 0; kk < 16; kk++) {
            unsigned long long a2[4];
#pragma unroll
            for (int mp = 0; mp < 4; mp++)
                a2[mp] = *(const unsigned long long*)&As[buf][kk][(ty << 3) + (mp << 1)];
            float4 b4 = *(const float4*)&Bs[buf][kk][tx << 2];
            unsigned long long b2[4];
            PACKX2(b2[0], b4.x); PACKX2(b2[1], b4.y);
            PACKX2(b2[2], b4.z); PACKX2(b2[3], b4.w);
#pragma unroll
            for (int mp = 0; mp < 4; mp++)
#pragma unroll
                for (int nn = 0; nn < 4; nn++)
                    FMAX2(acc[mp][nn], a2[mp], b2[nn]);
        }
        if (kt < 31) {
            __syncthreads();
            float va[4] = {av.x, av.y, av.z, av.w};
#pragma unroll
            for (int q = 0; q < 4; q++) {
                float2 al = ab[k0n + a_k4 + q];
                As[buf ^ 1][a_k4 + q][a_row] = fmaxf(fmaf(al.x, va[q], al.y), 0.f);
            }
            *(float4*)&Bs[buf ^ 1][b_row][b_col]     = bv0;
            *(float4*)&Bs[buf ^ 1][b_row][b_col + 4] = bv1;
            __syncthreads();
            buf ^= 1;
        }
    }

    // ---- fused epilogue: max/min over j + BN2 partial sums ----
    float tmax[4], tmin[4], tsum[4], tsq[4];
#pragma unroll
    for (int nn = 0; nn < 4; nn++) {
        tmax[nn] = -3.402823466e38f; tmin[nn] = 3.402823466e38f;
        tsum[nn] = 0.f; tsq[nn] = 0.f;
    }
#pragma unroll
    for (int mp = 0; mp < 4; mp++) {
#pragma unroll
        for (int nn = 0; nn < 4; nn++) {
            unsigned int lou, hiu;
            UNPACKX2(lou, hiu, acc[mp][nn]);
            float lo = __uint_as_float(lou), hi = __uint_as_float(hiu);
            tmax[nn] = fmaxf(tmax[nn], fmaxf(lo, hi));
            tmin[nn] = fminf(tmin[nn], fminf(lo, hi));
            tsum[nn] += lo + hi;
            tsq[nn]  = fmaf(lo, lo, fmaf(hi, hi, tsq[nn]));
        }
    }
#pragma unroll
    for (int nn = 0; nn < 4; nn++) {
        int cn = (tx << 2) + nn;
        rmax[ty][cn] = tmax[nn];
        rmin[ty][cn] = tmin[nn];
        rsum[ty][cn] = tsum[nn];
        rsq [ty][cn] = tsq[nn];
    }
    __syncthreads();
    if (tid < 128) {
        float mx = rmax[0][tid], mn = rmin[0][tid], sm = rsum[0][tid], sq = rsq[0][tid];
#pragma unroll
        for (int w = 1; w < 8; w++) {
            mx = fmaxf(mx, rmax[w][tid]);
            mn = fminf(mn, rmin[w][tid]);
            sm += rsum[w][tid];
            sq += rsq[w][tid];
        }
        g_maxZ[(size_t)si * D2 + n0 + tid] = mx;
        g_minZ[(size_t)si * D2 + n0 + tid] = mn;
        atomicAdd(&g_sum2[s * D2 + n0 + tid], sm);
        atomicAdd(&g_sq2 [s * D2 + n0 + tid], sq);
    }
}

// ---------------- K6: finalize BN2 ----------------
__global__ void k_bn2(const float* __restrict__ g2, const float* __restrict__ be2) {
    int idx = blockIdx.x * 256 + threadIdx.x;    // SQ*D2 = 32768
    if (idx >= SQ * D2) return;
    int d = idx & (D2 - 1);
    const float inv = 1.f / (float)PPRW;
    float m   = g_sum2[idx] * inv;
    float var = g_sq2[idx] * inv - m * m;
    float al  = g2[d] * rsqrtf(var + EPSV);
    g_ab2[idx] = make_float2(al, fmaf(-al, m, be2[d]));
}

// ---------------- K7: out = relu(alpha * (alpha>=0 ? max : min) + beta) ----------------
__global__ void k_out(float* __restrict__ out) {
    int idx = blockIdx.x * 256 + threadIdx.x;    // NB*D2 = 2M
    int si = idx >> 10;
    int d  = idx & (D2 - 1);
    int s  = si >> 6;
    float2 abv = g_ab2[s * D2 + d];
    float m = (abv.x >= 0.f) ? g_maxZ[idx] : g_minZ[idx];
    out[idx] = fmaxf(fmaf(abv.x, m, abv.y), 0.f);
}

// ---------------- launch ----------------
extern "C" void kernel_launch(void* const* d_in, const int* in_sizes, int n_in,
                              void* d_out, int out_size) {
    (void)in_sizes; (void)n_in; (void)out_size;
    const float* hs   = (const float*)d_in[0];
    // d_in[1] seq_start_end (uniform groups), d_in[2] end_pos (unused by ref), d_in[5] scalar: ignored
    const float* traj = (const float*)d_in[3];
    const float* tw   = (const float*)d_in[4];
    const float* Wsp  = (const float*)d_in[6];
    const float* bsp  = (const float*)d_in[7];
    const float* W1   = (const float*)d_in[8];
    // b1 (d_in[9]) cancels under BN mean-subtraction
    const float* g1   = (const float*)d_in[10];
    const float* be1  = (const float*)d_in[11];
    const float* W2   = (const float*)d_in[12];
    // b2 (d_in[13]) cancels under BN mean-subtraction
    const float* g2   = (const float*)d_in[14];
    const float* be2  = (const float*)d_in[15];
    float* out = (float*)d_out;

    k_zero <<<128, 256>>>();
    k_embed<<<NB, 128>>>(traj, Wsp, hs, W1);
    k_V    <<<4, 128>>>(bsp, W1);
    k_U    <<<NB / 8, 512>>>(W1);
    k_p1   <<<dim3(4, 64, SQ), 128>>>(tw);
    k_p2   <<<dim3(4, 64, SQ), 128>>>(tw);
    k_bn1  <<<64, 256>>>(g1, be1);
    k_gemm2<<<dim3(8, NB), 256>>>(W2);
    k_bn2  <<<128, 256>>>(g2, be2);
    k_out  <<<8192, 256>>>(out);
}

// round 7
// speedup vs baseline: 1.8714x; 1.8714x over previous
#include <cuda_runtime.h>
#include <cuda_bf16.h>
#include <cstdint>
#include <cstddef>

// ---------------- problem constants ----------------
#define SQ   32
#define PP64 64
#define NB   2048
#define PPRW 4096
#define D1   512
#define D2   1024
#define NKAP 16
#define EPSV 1e-5f

// ---------------- scratch ----------------
__device__ __align__(256) float g_a  [NB * 512];
__device__ __align__(256) float g_hW [NB * 512];
__device__ __align__(256) float g_U  [NB * NKAP * 512];
__device__ __align__(256) float g_V  [NKAP * 512];
__device__ __align__(256) float g_Z1 [(size_t)NB * PP64 * 512];   // 268 MB
__device__ float  g_sum1[SQ * 512];
__device__ float  g_sq1 [SQ * 512];
__device__ float2 g_ab1 [SQ * 512];
__device__ float  g_sum2[SQ * D2];
__device__ float  g_sq2 [SQ * D2];
__device__ float2 g_ab2 [SQ * D2];
__device__ __align__(256) float g_maxZ[NB * D2];
__device__ __align__(256) float g_minZ[NB * D2];
// bf16 split operands for HMMA GEMM2
__device__ __align__(256) __nv_bfloat16 g_Ah[(size_t)NB * PP64 * 512];  // 134 MB
__device__ __align__(256) __nv_bfloat16 g_Al[(size_t)NB * PP64 * 512];  // 134 MB
__device__ __align__(256) __nv_bfloat16 g_Bh[(size_t)D2 * 512];         // W2^T hi
__device__ __align__(256) __nv_bfloat16 g_Bl[(size_t)D2 * 512];         // W2^T lo

// ---------------- K0: zero BN accumulators ----------------
__global__ void k_zero() {
    int i = blockIdx.x * blockDim.x + threadIdx.x;
    if (i < SQ * 512) { g_sum1[i] = 0.f; g_sq1[i] = 0.f; }
    if (i < SQ * D2)  { g_sum2[i] = 0.f; g_sq2[i] = 0.f; }
}

// ---------------- K1: a = obs @ W_sp ; hW = h @ W1[512:576,:] ----------------
__global__ void k_embed(const float* __restrict__ traj, const float* __restrict__ Wsp,
                        const float* __restrict__ hs,   const float* __restrict__ W1) {
    int b = blockIdx.x;
    int tid = threadIdx.x;
    __shared__ float obs[16];
    __shared__ float hsh[64];
    if (tid < 16) {
        int t = tid >> 1, c = tid & 1;
        obs[tid] = traj[((size_t)t * NB + b) * 2 + c];
    }
    if (tid < 64) hsh[tid] = hs[b * 64 + tid];
    __syncthreads();
#pragma unroll
    for (int q = 0; q < 4; q++) {
        int f = tid + 128 * q;
        float acc = 0.f;
#pragma unroll
        for (int r = 0; r < 16; r++) acc = fmaf(obs[r], Wsp[r * 512 + f], acc);
        g_a[b * 512 + f] = acc;
        float ah = 0.f;
#pragma unroll
        for (int k = 0; k < 64; k++) ah = fmaf(hsh[k], W1[(512 + k) * 512 + f], ah);
        g_hW[b * 512 + f] = ah;
    }
}

// ---------------- K1b: V[kap][d] ----------------
__global__ void k_V(const float* __restrict__ bsp, const float* __restrict__ W1) {
    int d = blockIdx.x * 128 + threadIdx.x;
#pragma unroll
    for (int kap = 0; kap < NKAP; kap++) {
        int par = kap >> 3, t = kap & 7;
        float acc = 0.f;
#pragma unroll 4
        for (int e = par; e < 64; e += 2) {
            int f = t * 64 + e;
            acc = fmaf(bsp[f], W1[f * 512 + d], acc);
        }
        g_V[kap * 512 + d] = acc;
    }
}

// ---------------- K2: U[b][kap][d]; 16 peds/block ----------------
__global__ void k_U(const float* __restrict__ W1) {
    int b0 = blockIdx.x * 16;
    int d  = threadIdx.x;
    __shared__ float a[16][512];
    for (int idx = threadIdx.x; idx < 16 * 512; idx += 512)
        a[idx >> 9][idx & 511] = g_a[b0 * 512 + idx];
    __syncthreads();
#pragma unroll 1
    for (int kap = 0; kap < NKAP; kap++) {
        int par = kap >> 3, t = kap & 7;
        float acc[16];
#pragma unroll
        for (int bb = 0; bb < 16; bb++) acc[bb] = 0.f;
#pragma unroll 8
        for (int e = par; e < 64; e += 2) {
            int f = t * 64 + e;
            float w1 = W1[f * 512 + d];
#pragma unroll
            for (int bb = 0; bb < 16; bb++) acc[bb] = fmaf(a[bb][f], w1, acc[bb]);
        }
#pragma unroll
        for (int bb = 0; bb < 16; bb++)
            g_U[(size_t)((b0 + bb) * NKAP + kap) * 512 + d] = acc[bb];
    }
}

// ---------------- K2b: W2^T -> bf16 hi/lo ----------------
__global__ void k_wconv(const float* __restrict__ W2) {
    __shared__ float t[32][33];
    int k0 = blockIdx.x * 32, n0 = blockIdx.y * 32;
    int tx = threadIdx.x, ty = threadIdx.y;
#pragma unroll
    for (int r = 0; r < 32; r += 8)
        t[ty + r][tx] = W2[(size_t)(k0 + ty + r) * D2 + n0 + tx];
    __syncthreads();
#pragma unroll
    for (int r = 0; r < 32; r += 8) {
        float v = t[tx][ty + r];
        __nv_bfloat16 hi = __float2bfloat16(v);
        __nv_bfloat16 lo = __float2bfloat16(v - __bfloat162float(hi));
        size_t o = (size_t)(n0 + ty + r) * 512 + k0 + tx;
        g_Bh[o] = hi; g_Bl[o] = lo;
    }
}

// ---------------- K3a / K3b: Z1 build + BN1 stats ----------------
__global__ void k_p1(const float* __restrict__ tw) {
    int tid = threadIdx.x;
    int dt = blockIdx.x, j = blockIdx.y, s = blockIdx.z;
    int d  = (dt << 7) + tid;
    int bj = (s << 6) + j;
    __shared__ float wsh[64][16];
    for (int idx = tid; idx < 1024; idx += 128) {
        int i = idx >> 4, kap = idx & 15;
        wsh[i][kap] = tw[(size_t)((s << 12) + (i << 6) + j) * 16 + kap];
    }
    float uj[16];
#pragma unroll
    for (int kap = 0; kap < 16; kap++)
        uj[kap] = g_U[(size_t)((bj << 4) + kap) * 512 + d];
    float hwj = g_hW[bj * 512 + d];
    __syncthreads();
    float* zbase = g_Z1 + (size_t)((s << 12) + j) * 512 + d;
#pragma unroll 4
    for (int i = 0; i < 64; i++) {
        float acc = hwj;
#pragma unroll
        for (int kap = 0; kap < 16; kap++) acc = fmaf(wsh[i][kap], uj[kap], acc);
        zbase[(size_t)i * (64 * 512)] = acc;
    }
}

__global__ void k_p2(const float* __restrict__ tw) {
    int tid = threadIdx.x;
    int dt = blockIdx.x, i = blockIdx.y, s = blockIdx.z;
    int d  = (dt << 7) + tid;
    int bi = (s << 6) + i;
    __shared__ float wsh[64][16];
    for (int idx = tid; idx < 1024; idx += 128)
        ((float*)wsh)[idx] = tw[(size_t)((s << 12) + (i << 6)) * 16 + idx];
    float vu[16];
#pragma unroll
    for (int kap = 0; kap < 16; kap++)
        vu[kap] = g_V[(kap << 9) + d] - g_U[(size_t)((bi << 4) + kap) * 512 + d];
    __syncthreads();
    float lsum = 0.f, lsq = 0.f;
    float* zbase = g_Z1 + (size_t)((s << 12) + (i << 6)) * 512 + d;
#pragma unroll 4
    for (int j = 0; j < 64; j++) {
        float acc = 0.f;
#pragma unroll
        for (int kap = 0; kap < 16; kap++) acc = fmaf(wsh[j][kap], vu[kap], acc);
        float z = zbase[(size_t)j * 512] + acc;
        zbase[(size_t)j * 512] = z;
        lsum += z;
        lsq  = fmaf(z, z, lsq);
    }
    atomicAdd(&g_sum1[(s << 9) + d], lsum);
    atomicAdd(&g_sq1 [(s << 9) + d], lsq);
}

// ---------------- K4: finalize BN1 ----------------
__global__ void k_bn1(const float* __restrict__ g1, const float* __restrict__ be1) {
    int idx = blockIdx.x * 256 + threadIdx.x;
    if (idx >= SQ * 512) return;
    int d = idx & 511;
    const float inv = 1.f / (float)PPRW;
    float m   = g_sum1[idx] * inv;
    float var = g_sq1[idx] * inv - m * m;
    float al  = g1[d] * rsqrtf(var + EPSV);
    g_ab1[idx] = make_float2(al, fmaf(-al, m, be1[d]));
}

// ---------------- K4b: A1 = relu(bn1(Z1)) -> bf16 hi/lo split ----------------
__global__ void k_conv() {
    size_t idx = ((size_t)blockIdx.x * 256 + threadIdx.x) * 4;
    float4 z = *(const float4*)(g_Z1 + idx);
    int d = (int)(idx & 511);
    int s = (int)(idx >> 21);
    const float2* abp = g_ab1 + (s << 9) + d;
    float v[4] = {z.x, z.y, z.z, z.w};
    __nv_bfloat16 hi[4], lo[4];
#pragma unroll
    for (int q = 0; q < 4; q++) {
        float2 ab = abp[q];
        float a1 = fmaxf(fmaf(ab.x, v[q], ab.y), 0.f);
        hi[q] = __float2bfloat16(a1);
        lo[q] = __float2bfloat16(a1 - __bfloat162float(hi[q]));
    }
    __nv_bfloat162* ph = (__nv_bfloat162*)(g_Ah + idx);
    __nv_bfloat162* pl = (__nv_bfloat162*)(g_Al + idx);
    ph[0] = __nv_bfloat162(hi[0], hi[1]); ph[1] = __nv_bfloat162(hi[2], hi[3]);
    pl[0] = __nv_bfloat162(lo[0], lo[1]); pl[1] = __nv_bfloat162(lo[2], lo[3]);
}

// ---------------- K5: HMMA bf16 split GEMM2 ---------------------------------
// CTA: M=128 (2 si groups x 64 j), N=128, K=512 (BK=32), 3-term bf16 split.
// mma.sync.aligned.m16n8k16.row.col.f32.bf16.bf16.f32 (base sm_80+ ISA).
#define BK     32
#define APITCH 40                       // bf16 elems per smem row (bank-perm 20 words)
#define TILE_B (128 * APITCH * 2)       // 10240 B per operand tile
#define BUF_B  (4 * TILE_B)             // Ah,Al,Bh,Bl per buffer = 40960 B
#define GT2_SMEM (2 * BUF_B)            // 81920 B

__device__ __forceinline__ void mma16816(float* c, const uint32_t* a, const uint32_t* b) {
    asm volatile("mma.sync.aligned.m16n8k16.row.col.f32.bf16.bf16.f32 "
                 "{%0,%1,%2,%3}, {%4,%5,%6,%7}, {%8,%9}, {%0,%1,%2,%3};"
                 : "+f"(c[0]), "+f"(c[1]), "+f"(c[2]), "+f"(c[3])
                 : "r"(a[0]), "r"(a[1]), "r"(a[2]), "r"(a[3]), "r"(b[0]), "r"(b[1]));
}

__global__ void __launch_bounds__(256) k_gemm2m() {
    extern __shared__ __align__(16) char smem[];
    const int tid  = threadIdx.x;
    const int wid  = tid >> 5;
    const int lane = tid & 31;
    const int wy   = wid & 3;           // M: 32*wy
    const int wx   = wid >> 2;          // N: 64*wx
    const int g    = lane >> 2;         // groupID
    const int t    = lane & 3;          // thread-in-group
    const int nblk = blockIdx.x;        // 0..7
    const int mblk = blockIdx.y;        // 0..1023
    const int n0   = nblk << 7;
    const size_t arow0 = (size_t)mblk << 7;   // 128 rows
    const int si0  = mblk << 1;

    float c[2][8][4];
#pragma unroll
    for (int mt = 0; mt < 2; mt++)
#pragma unroll
        for (int nt = 0; nt < 8; nt++)
#pragma unroll
            for (int r = 0; r < 4; r++) c[mt][nt][r] = 0.f;

    // cp.async one chunk (A/B hi+lo 128x32 bf16 tiles) into buffer
#define ISSUE(c_, buf_) do {                                                   \
    int _k0 = (c_) << 5;                                                       \
    char* _bb = smem + (buf_) * BUF_B;                                         \
    _Pragma("unroll")                                                          \
    for (int _q = 0; _q < 8; _q++) {                                           \
        int _seg = tid + (_q << 8);                                            \
        int _tile = _seg >> 9;                                                 \
        int _r = (_seg >> 2) & 127;                                            \
        int _qq = _seg & 3;                                                    \
        const __nv_bfloat16* _src;                                             \
        if (_tile == 0)      _src = g_Ah + ((arow0 + _r) << 9) + _k0 + (_qq << 3); \
        else if (_tile == 1) _src = g_Al + ((arow0 + _r) << 9) + _k0 + (_qq << 3); \
        else if (_tile == 2) _src = g_Bh + ((size_t)(n0 + _r) << 9) + _k0 + (_qq << 3); \
        else                 _src = g_Bl + ((size_t)(n0 + _r) << 9) + _k0 + (_qq << 3); \
        uint32_t _dst;                                                         \
        asm("{ .reg .u64 t; cvta.to.shared.u64 t, %1; cvt.u32.u64 %0, t; }"    \
            : "=r"(_dst) : "l"(_bb + _tile * TILE_B + _r * (APITCH * 2) + (_qq << 4))); \
        asm volatile("cp.async.cg.shared.global [%0], [%1], 16;"               \
                     :: "r"(_dst), "l"(_src));                                 \
    }                                                                          \
    asm volatile("cp.async.commit_group;" ::: "memory");                       \
} while (0)

    ISSUE(0, 0);

    for (int ch = 0; ch < 16; ch++) {
        const int buf = ch & 1;
        if (ch < 15) {
            ISSUE(ch + 1, buf ^ 1);
            asm volatile("cp.async.wait_group 1;" ::: "memory");
        } else {
            asm volatile("cp.async.wait_group 0;" ::: "memory");
        }
        __syncthreads();

        const __nv_bfloat16* Ah_s = (const __nv_bfloat16*)(smem + buf * BUF_B);
        const __nv_bfloat16* Al_s = (const __nv_bfloat16*)(smem + buf * BUF_B + TILE_B);
        const __nv_bfloat16* Bh_s = (const __nv_bfloat16*)(smem + buf * BUF_B + 2 * TILE_B);
        const __nv_bfloat16* Bl_s = (const __nv_bfloat16*)(smem + buf * BUF_B + 3 * TILE_B);

#pragma unroll
        for (int ks = 0; ks < 2; ks++) {
            const int k16 = ks << 4;
            uint32_t ah[2][4], al[2][4], bh[8][2], bl[8][2];
#pragma unroll
            for (int mt = 0; mt < 2; mt++) {
                int m = (wy << 5) + (mt << 4);
                ah[mt][0] = *(const uint32_t*)&Ah_s[(m + g)     * APITCH + k16 + 2 * t];
                ah[mt][1] = *(const uint32_t*)&Ah_s[(m + 8 + g) * APITCH + k16 + 2 * t];
                ah[mt][2] = *(const uint32_t*)&Ah_s[(m + g)     * APITCH + k16 + 8 + 2 * t];
                ah[mt][3] = *(const uint32_t*)&Ah_s[(m + 8 + g) * APITCH + k16 + 8 + 2 * t];
                al[mt][0] = *(const uint32_t*)&Al_s[(m + g)     * APITCH + k16 + 2 * t];
                al[mt][1] = *(const uint32_t*)&Al_s[(m + 8 + g) * APITCH + k16 + 2 * t];
                al[mt][2] = *(const uint32_t*)&Al_s[(m + g)     * APITCH + k16 + 8 + 2 * t];
                al[mt][3] = *(const uint32_t*)&Al_s[(m + 8 + g) * APITCH + k16 + 8 + 2 * t];
            }
#pragma unroll
            for (int nt = 0; nt < 8; nt++) {
                int n = (wx << 6) + (nt << 3);
                bh[nt][0] = *(const uint32_t*)&Bh_s[(n + g) * APITCH + k16 + 2 * t];
                bh[nt][1] = *(const uint32_t*)&Bh_s[(n + g) * APITCH + k16 + 8 + 2 * t];
                bl[nt][0] = *(const uint32_t*)&Bl_s[(n + g) * APITCH + k16 + 2 * t];
                bl[nt][1] = *(const uint32_t*)&Bl_s[(n + g) * APITCH + k16 + 8 + 2 * t];
            }
#pragma unroll
            for (int nt = 0; nt < 8; nt++)
#pragma unroll
                for (int mt = 0; mt < 2; mt++) {
                    mma16816(c[mt][nt], ah[mt], bh[nt]);
                    mma16816(c[mt][nt], al[mt], bh[nt]);
                    mma16816(c[mt][nt], ah[mt], bl[nt]);
                }
        }
        __syncthreads();
    }
#undef ISSUE

    // ---- epilogue: column-wise max/min/sum/sq over this warp's 32 rows ----
    float* s_mx = (float*)smem;            // [8][64]
    float* s_mn = s_mx + 512;
    float* s_sm = s_mn + 512;
    float* s_sq = s_sm + 512;

#pragma unroll
    for (int nt = 0; nt < 8; nt++) {
#pragma unroll
        for (int b = 0; b < 2; b++) {      // col = nt*8 + 2t + b; regs {b, b+2}
            float mx = fmaxf(fmaxf(c[0][nt][b], c[0][nt][b + 2]),
                             fmaxf(c[1][nt][b], c[1][nt][b + 2]));
            float mn = fminf(fminf(c[0][nt][b], c[0][nt][b + 2]),
                             fminf(c[1][nt][b], c[1][nt][b + 2]));
            float sm = c[0][nt][b] + c[0][nt][b + 2] + c[1][nt][b] + c[1][nt][b + 2];
            float sq = c[0][nt][b] * c[0][nt][b] + c[0][nt][b + 2] * c[0][nt][b + 2]
                     + c[1][nt][b] * c[1][nt][b] + c[1][nt][b + 2] * c[1][nt][b + 2];
#pragma unroll
            for (int o = 4; o < 32; o <<= 1) {
                mx = fmaxf(mx, __shfl_xor_sync(0xffffffffu, mx, o));
                mn = fminf(mn, __shfl_xor_sync(0xffffffffu, mn, o));
                sm += __shfl_xor_sync(0xffffffffu, sm, o);
                sq += __shfl_xor_sync(0xffffffffu, sq, o);
            }
            if (g == 0) {
                int cl = wid * 64 + (nt << 3) + 2 * t + b;
                s_mx[cl] = mx; s_mn[cl] = mn; s_sm[cl] = sm; s_sq[cl] = sq;
            }
        }
    }
    __syncthreads();

    {   // max/min per (jg, col): combine warp pair (wy = 2jg, 2jg+1) at wx = col>>6
        int jg = tid >> 7, col = tid & 127;
        int wxx = col >> 6, c64 = col & 63;
        int w0 = (wxx << 2) + (jg << 1);
        float mx = fmaxf(s_mx[w0 * 64 + c64], s_mx[(w0 + 1) * 64 + c64]);
        float mn = fminf(s_mn[w0 * 64 + c64], s_mn[(w0 + 1) * 64 + c64]);
        int si = si0 + jg;
        g_maxZ[(size_t)si * D2 + n0 + col] = mx;
        g_minZ[(size_t)si * D2 + n0 + col] = mn;
    }
    if (tid < 128) {   // BN2 partials: sum over all 128 rows (both jg share s)
        int col = tid, wxx = col >> 6, c64 = col & 63;
        float sm = 0.f, sq = 0.f;
#pragma unroll
        for (int w = 0; w < 4; w++) {
            sm += s_sm[((wxx << 2) + w) * 64 + c64];
            sq += s_sq[((wxx << 2) + w) * 64 + c64];
        }
        int s_ = si0 >> 6;
        atomicAdd(&g_sum2[s_ * D2 + n0 + col], sm);
        atomicAdd(&g_sq2 [s_ * D2 + n0 + col], sq);
    }
}

// ---------------- K6: finalize BN2 ----------------
__global__ void k_bn2(const float* __restrict__ g2, const float* __restrict__ be2) {
    int idx = blockIdx.x * 256 + threadIdx.x;
    if (idx >= SQ * D2) return;
    int d = idx & (D2 - 1);
    const float inv = 1.f / (float)PPRW;
    float m   = g_sum2[idx] * inv;
    float var = g_sq2[idx] * inv - m * m;
    float al  = g2[d] * rsqrtf(var + EPSV);
    g_ab2[idx] = make_float2(al, fmaf(-al, m, be2[d]));
}

// ---------------- K7: out = relu(alpha * (alpha>=0 ? max : min) + beta) ----------------
__global__ void k_out(float* __restrict__ out) {
    int idx = blockIdx.x * 256 + threadIdx.x;
    int si = idx >> 10;
    int d  = idx & (D2 - 1);
    int s  = si >> 6;
    float2 abv = g_ab2[s * D2 + d];
    float m = (abv.x >= 0.f) ? g_maxZ[idx] : g_minZ[idx];
    out[idx] = fmaxf(fmaf(abv.x, m, abv.y), 0.f);
}

// ---------------- launch ----------------
extern "C" void kernel_launch(void* const* d_in, const int* in_sizes, int n_in,
                              void* d_out, int out_size) {
    (void)in_sizes; (void)n_in; (void)out_size;
    const float* hs   = (const float*)d_in[0];
    const float* traj = (const float*)d_in[3];
    const float* tw   = (const float*)d_in[4];
    const float* Wsp  = (const float*)d_in[6];
    const float* bsp  = (const float*)d_in[7];
    const float* W1   = (const float*)d_in[8];
    const float* g1   = (const float*)d_in[10];
    const float* be1  = (const float*)d_in[11];
    const float* W2   = (const float*)d_in[12];
    const float* g2   = (const float*)d_in[14];
    const float* be2  = (const float*)d_in[15];
    float* out = (float*)d_out;

    cudaFuncSetAttribute(k_gemm2m, cudaFuncAttributeMaxDynamicSharedMemorySize, GT2_SMEM);

    k_zero <<<128, 256>>>();
    k_embed<<<NB, 128>>>(traj, Wsp, hs, W1);
    k_V    <<<4, 128>>>(bsp, W1);
    k_U    <<<NB / 16, 512>>>(W1);
    k_wconv<<<dim3(16, 32), dim3(32, 8)>>>(W2);
    k_p1   <<<dim3(4, 64, SQ), 128>>>(tw);
    k_p2   <<<dim3(4, 64, SQ), 128>>>(tw);
    k_bn1  <<<64, 256>>>(g1, be1);
    k_conv <<<65536, 256>>>();
    k_gemm2m<<<dim3(8, 1024), 256, GT2_SMEM>>>();
    k_bn2  <<<128, 256>>>(g2, be2);
    k_out  <<<8192, 256>>>(out);
}

// round 8
// speedup vs baseline: 1.9249x; 1.0286x over previous
#include <cuda_runtime.h>
#include <cuda_bf16.h>
#include <cstdint>
#include <cstddef>

// ---------------- problem constants ----------------
#define SQ   32
#define PP64 64
#define NB   2048
#define PPRW 4096
#define D1   512
#define D2   1024
#define NKAP 16
#define EPSV 1e-5f

// ---------------- scratch ----------------
__device__ __align__(256) float g_a  [NB * 512];
__device__ __align__(256) float g_hW [NB * 512];
__device__ __align__(256) float g_U  [NB * NKAP * 512];
__device__ __align__(256) float g_V  [NKAP * 512];
__device__ __align__(256) float g_Z1 [(size_t)NB * PP64 * 512];   // 268 MB
__device__ float  g_sum1[SQ * 512];
__device__ float  g_sq1 [SQ * 512];
__device__ float2 g_ab1 [SQ * 512];
__device__ float  g_sum2[SQ * D2];
__device__ float  g_sq2 [SQ * D2];
__device__ float2 g_ab2 [SQ * D2];
__device__ __align__(256) float g_maxZ[NB * D2];
__device__ __align__(256) float g_minZ[NB * D2];
// bf16 split operands for HMMA GEMM2
__device__ __align__(256) __nv_bfloat16 g_Ah[(size_t)NB * PP64 * 512];  // 134 MB
__device__ __align__(256) __nv_bfloat16 g_Al[(size_t)NB * PP64 * 512];  // 134 MB
__device__ __align__(256) __nv_bfloat16 g_Bh[(size_t)D2 * 512];         // W2^T hi
__device__ __align__(256) __nv_bfloat16 g_Bl[(size_t)D2 * 512];         // W2^T lo

__device__ __forceinline__ uint32_t smem_u32(const void* p) {
    uint32_t a;
    asm("{ .reg .u64 t; cvta.to.shared.u64 t, %1; cvt.u32.u64 %0, t; }" : "=r"(a) : "l"(p));
    return a;
}

// ---------------- K0: zero BN accumulators ----------------
__global__ void k_zero() {
    int i = blockIdx.x * blockDim.x + threadIdx.x;
    if (i < SQ * 512) { g_sum1[i] = 0.f; g_sq1[i] = 0.f; }
    if (i < SQ * D2)  { g_sum2[i] = 0.f; g_sq2[i] = 0.f; }
}

// ---------------- K1: a = obs @ W_sp ; hW = h @ W1[512:576,:] ----------------
__global__ void k_embed(const float* __restrict__ traj, const float* __restrict__ Wsp,
                        const float* __restrict__ hs,   const float* __restrict__ W1) {
    int b = blockIdx.x;
    int tid = threadIdx.x;
    __shared__ float obs[16];
    __shared__ float hsh[64];
    if (tid < 16) {
        int t = tid >> 1, c = tid & 1;
        obs[tid] = traj[((size_t)t * NB + b) * 2 + c];
    }
    if (tid < 64) hsh[tid] = hs[b * 64 + tid];
    __syncthreads();
#pragma unroll
    for (int q = 0; q < 4; q++) {
        int f = tid + 128 * q;
        float acc = 0.f;
#pragma unroll
        for (int r = 0; r < 16; r++) acc = fmaf(obs[r], Wsp[r * 512 + f], acc);
        g_a[b * 512 + f] = acc;
        float ah = 0.f;
#pragma unroll
        for (int k = 0; k < 64; k++) ah = fmaf(hsh[k], W1[(512 + k) * 512 + f], ah);
        g_hW[b * 512 + f] = ah;
    }
}

// ---------------- K1b: V[kap][d] ----------------
__global__ void k_V(const float* __restrict__ bsp, const float* __restrict__ W1) {
    int d = blockIdx.x * 128 + threadIdx.x;
#pragma unroll
    for (int kap = 0; kap < NKAP; kap++) {
        int par = kap >> 3, t = kap & 7;
        float acc = 0.f;
#pragma unroll 4
        for (int e = par; e < 64; e += 2) {
            int f = t * 64 + e;
            acc = fmaf(bsp[f], W1[f * 512 + d], acc);
        }
        g_V[kap * 512 + d] = acc;
    }
}

// ---------------- K2: U[b][kap][d]; 8 peds x 4 d per thread ----------------
__global__ void k_U(const float* __restrict__ W1) {
    int b0 = blockIdx.x * 8;            // grid 256
    int tid = threadIdx.x;              // 128
    int d0 = tid << 2;                  // 4 d per thread
    __shared__ float a[8][512];
    for (int idx = tid; idx < 1024; idx += 128) {
        int bb = idx >> 7, c4 = (idx & 127) << 2;
        *(float4*)&a[bb][c4] = *(const float4*)&g_a[(b0 + bb) * 512 + c4];
    }
    __syncthreads();
#pragma unroll 1
    for (int kap = 0; kap < NKAP; kap++) {
        int par = kap >> 3, t = kap & 7;
        float4 acc[8];
#pragma unroll
        for (int bb = 0; bb < 8; bb++) acc[bb] = make_float4(0.f, 0.f, 0.f, 0.f);
#pragma unroll 8
        for (int e = par; e < 64; e += 2) {
            int f = t * 64 + e;
            float4 w = *(const float4*)&W1[f * 512 + d0];
#pragma unroll
            for (int bb = 0; bb < 8; bb++) {
                float av = a[bb][f];
                acc[bb].x = fmaf(av, w.x, acc[bb].x);
                acc[bb].y = fmaf(av, w.y, acc[bb].y);
                acc[bb].z = fmaf(av, w.z, acc[bb].z);
                acc[bb].w = fmaf(av, w.w, acc[bb].w);
            }
        }
#pragma unroll
        for (int bb = 0; bb < 8; bb++)
            *(float4*)&g_U[(size_t)((b0 + bb) * NKAP + kap) * 512 + d0] = acc[bb];
    }
}

// ---------------- K2b: W2^T -> bf16 hi/lo ----------------
__global__ void k_wconv(const float* __restrict__ W2) {
    __shared__ float t[32][33];
    int k0 = blockIdx.x * 32, n0 = blockIdx.y * 32;
    int tx = threadIdx.x, ty = threadIdx.y;
#pragma unroll
    for (int r = 0; r < 32; r += 8)
        t[ty + r][tx] = W2[(size_t)(k0 + ty + r) * D2 + n0 + tx];
    __syncthreads();
#pragma unroll
    for (int r = 0; r < 32; r += 8) {
        float v = t[tx][ty + r];
        __nv_bfloat16 hi = __float2bfloat16(v);
        __nv_bfloat16 lo = __float2bfloat16(v - __bfloat162float(hi));
        size_t o = (size_t)(n0 + ty + r) * 512 + k0 + tx;
        g_Bh[o] = hi; g_Bl[o] = lo;
    }
}

// ---------------- K3a / K3b: Z1 build + BN1 stats ----------------
__global__ void k_p1(const float* __restrict__ tw) {
    int tid = threadIdx.x;
    int dt = blockIdx.x, j = blockIdx.y, s = blockIdx.z;
    int d  = (dt << 7) + tid;
    int bj = (s << 6) + j;
    __shared__ float wsh[64][16];
    for (int idx = tid; idx < 1024; idx += 128) {
        int i = idx >> 4, kap = idx & 15;
        wsh[i][kap] = tw[(size_t)((s << 12) + (i << 6) + j) * 16 + kap];
    }
    float uj[16];
#pragma unroll
    for (int kap = 0; kap < 16; kap++)
        uj[kap] = g_U[(size_t)((bj << 4) + kap) * 512 + d];
    float hwj = g_hW[bj * 512 + d];
    __syncthreads();
    float* zbase = g_Z1 + (size_t)((s << 12) + j) * 512 + d;
#pragma unroll 4
    for (int i = 0; i < 64; i++) {
        float acc = hwj;
#pragma unroll
        for (int kap = 0; kap < 16; kap++) acc = fmaf(wsh[i][kap], uj[kap], acc);
        zbase[(size_t)i * (64 * 512)] = acc;
    }
}

__global__ void k_p2(const float* __restrict__ tw) {
    int tid = threadIdx.x;
    int dt = blockIdx.x, i = blockIdx.y, s = blockIdx.z;
    int d  = (dt << 7) + tid;
    int bi = (s << 6) + i;
    __shared__ float wsh[64][16];
    for (int idx = tid; idx < 1024; idx += 128)
        ((float*)wsh)[idx] = tw[(size_t)((s << 12) + (i << 6)) * 16 + idx];
    float vu[16];
#pragma unroll
    for (int kap = 0; kap < 16; kap++)
        vu[kap] = g_V[(kap << 9) + d] - g_U[(size_t)((bi << 4) + kap) * 512 + d];
    __syncthreads();
    float lsum = 0.f, lsq = 0.f;
    float* zbase = g_Z1 + (size_t)((s << 12) + (i << 6)) * 512 + d;
#pragma unroll 4
    for (int j = 0; j < 64; j++) {
        float acc = 0.f;
#pragma unroll
        for (int kap = 0; kap < 16; kap++) acc = fmaf(wsh[j][kap], vu[kap], acc);
        float z = zbase[(size_t)j * 512] + acc;
        zbase[(size_t)j * 512] = z;
        lsum += z;
        lsq  = fmaf(z, z, lsq);
    }
    atomicAdd(&g_sum1[(s << 9) + d], lsum);
    atomicAdd(&g_sq1 [(s << 9) + d], lsq);
}

// ---------------- K4: finalize BN1 ----------------
__global__ void k_bn1(const float* __restrict__ g1, const float* __restrict__ be1) {
    int idx = blockIdx.x * 256 + threadIdx.x;
    if (idx >= SQ * 512) return;
    int d = idx & 511;
    const float inv = 1.f / (float)PPRW;
    float m   = g_sum1[idx] * inv;
    float var = g_sq1[idx] * inv - m * m;
    float al  = g1[d] * rsqrtf(var + EPSV);
    g_ab1[idx] = make_float2(al, fmaf(-al, m, be1[d]));
}

// ---------------- K4b: A1 = relu(bn1(Z1)) -> bf16 hi/lo split ----------------
__global__ void k_conv() {
    size_t idx = ((size_t)blockIdx.x * 256 + threadIdx.x) * 4;
    float4 z = *(const float4*)(g_Z1 + idx);
    int d = (int)(idx & 511);
    int s = (int)(idx >> 21);
    const float2* abp = g_ab1 + (s << 9) + d;
    float v[4] = {z.x, z.y, z.z, z.w};
    __nv_bfloat16 hi[4], lo[4];
#pragma unroll
    for (int q = 0; q < 4; q++) {
        float2 ab = abp[q];
        float a1 = fmaxf(fmaf(ab.x, v[q], ab.y), 0.f);
        hi[q] = __float2bfloat16(a1);
        lo[q] = __float2bfloat16(a1 - __bfloat162float(hi[q]));
    }
    __nv_bfloat162* ph = (__nv_bfloat162*)(g_Ah + idx);
    __nv_bfloat162* pl = (__nv_bfloat162*)(g_Al + idx);
    ph[0] = __nv_bfloat162(hi[0], hi[1]); ph[1] = __nv_bfloat162(hi[2], hi[3]);
    pl[0] = __nv_bfloat162(lo[0], lo[1]); pl[1] = __nv_bfloat162(lo[2], lo[3]);
}

// ---------------- K5: HMMA bf16 split GEMM2 (ldmatrix + phased terms) -------
#define BK     32
#define APITCH 40                       // bf16 elems per smem row (bank-perm)
#define TILE_B (128 * APITCH * 2)       // 10240 B per operand tile
#define BUF_B  (4 * TILE_B)             // Ah,Al,Bh,Bl = 40960 B
#define GT2_SMEM (2 * BUF_B)            // 81920 B

__device__ __forceinline__ void mma16816(float* c, const uint32_t* a, const uint32_t* b) {
    asm volatile("mma.sync.aligned.m16n8k16.row.col.f32.bf16.bf16.f32 "
                 "{%0,%1,%2,%3}, {%4,%5,%6,%7}, {%8,%9}, {%0,%1,%2,%3};"
                 : "+f"(c[0]), "+f"(c[1]), "+f"(c[2]), "+f"(c[3])
                 : "r"(a[0]), "r"(a[1]), "r"(a[2]), "r"(a[3]), "r"(b[0]), "r"(b[1]));
}
#define LDSM_X4(r, addr) \
    asm volatile("ldmatrix.sync.aligned.m8n8.x4.shared.b16 {%0,%1,%2,%3}, [%4];" \
        : "=r"((r)[0]), "=r"((r)[1]), "=r"((r)[2]), "=r"((r)[3]) : "r"(addr))

__global__ void __launch_bounds__(256, 2) k_gemm2m() {
    extern __shared__ __align__(16) char smem[];
    const uint32_t sb = smem_u32(smem);
    const int tid  = threadIdx.x;
    const int wid  = tid >> 5;
    const int lane = tid & 31;
    const int wy   = wid & 3;           // M: 32*wy
    const int wx   = wid >> 2;          // N: 64*wx
    const int g    = lane >> 2;
    const int t    = lane & 3;
    const int nblk = blockIdx.x;        // 0..7
    const int mblk = blockIdx.y;        // 0..1023
    const int n0   = nblk << 7;
    const size_t arow0 = (size_t)mblk << 7;
    const int si0  = mblk << 1;

    // ldmatrix per-lane offsets (bytes, relative to tile start)
    const int mrow  = ((lane >> 3) & 1) * 8 + (lane & 7);
    const int kselA = (lane >> 4) << 3;
    const int browB = ((lane >> 4) << 3) + (lane & 7);
    const int kselB = ((lane >> 3) & 1) << 3;
    uint32_t offA[2][2], offB[4][2];
#pragma unroll
    for (int mt = 0; mt < 2; mt++)
#pragma unroll
        for (int ks = 0; ks < 2; ks++)
            offA[mt][ks] = (uint32_t)(((wy * 32 + mt * 16 + mrow) * APITCH + ks * 16 + kselA) * 2);
#pragma unroll
    for (int np = 0; np < 4; np++)
#pragma unroll
        for (int ks = 0; ks < 2; ks++)
            offB[np][ks] = (uint32_t)(((wx * 64 + np * 16 + browB) * APITCH + ks * 16 + kselB) * 2);

    float c[2][8][4];
#pragma unroll
    for (int mt = 0; mt < 2; mt++)
#pragma unroll
        for (int nt = 0; nt < 8; nt++)
#pragma unroll
            for (int r = 0; r < 4; r++) c[mt][nt][r] = 0.f;

#define ISSUE(c_, buf_) do {                                                   \
    int _k0 = (c_) << 5;                                                       \
    char* _bb = smem + (buf_) * BUF_B;                                         \
    _Pragma("unroll")                                                          \
    for (int _q = 0; _q < 8; _q++) {                                           \
        int _seg = tid + (_q << 8);                                            \
        int _tile = _seg >> 9;                                                 \
        int _r = (_seg >> 2) & 127;                                            \
        int _qq = _seg & 3;                                                    \
        const __nv_bfloat16* _src;                                             \
        if (_tile == 0)      _src = g_Ah + ((arow0 + _r) << 9) + _k0 + (_qq << 3); \
        else if (_tile == 1) _src = g_Al + ((arow0 + _r) << 9) + _k0 + (_qq << 3); \
        else if (_tile == 2) _src = g_Bh + ((size_t)(n0 + _r) << 9) + _k0 + (_qq << 3); \
        else                 _src = g_Bl + ((size_t)(n0 + _r) << 9) + _k0 + (_qq << 3); \
        uint32_t _dst;                                                         \
        asm("{ .reg .u64 t; cvta.to.shared.u64 t, %1; cvt.u32.u64 %0, t; }"    \
            : "=r"(_dst) : "l"(_bb + _tile * TILE_B + _r * (APITCH * 2) + (_qq << 4))); \
        asm volatile("cp.async.cg.shared.global [%0], [%1], 16;"               \
                     :: "r"(_dst), "l"(_src));                                 \
    }                                                                          \
    asm volatile("cp.async.commit_group;" ::: "memory");                       \
} while (0)

    ISSUE(0, 0);

    for (int ch = 0; ch < 16; ch++) {
        const int buf = ch & 1;
        if (ch < 15) {
            ISSUE(ch + 1, buf ^ 1);
            asm volatile("cp.async.wait_group 1;" ::: "memory");
        } else {
            asm volatile("cp.async.wait_group 0;" ::: "memory");
        }
        __syncthreads();

        const uint32_t tb = sb + buf * BUF_B;
#pragma unroll
        for (int ks = 0; ks < 2; ks++) {
            uint32_t ah[2][4], ax[2][4], bx[8][2];
            // phase 1: Ah * Bh
#pragma unroll
            for (int mt = 0; mt < 2; mt++) LDSM_X4(ah[mt], tb + offA[mt][ks]);
#pragma unroll
            for (int np = 0; np < 4; np++) LDSM_X4(&bx[2 * np][0], tb + 2 * TILE_B + offB[np][ks]);
#pragma unroll
            for (int nt = 0; nt < 8; nt++)
#pragma unroll
                for (int mt = 0; mt < 2; mt++) mma16816(c[mt][nt], ah[mt], bx[nt]);
            // phase 2: Al * Bh
#pragma unroll
            for (int mt = 0; mt < 2; mt++) LDSM_X4(ax[mt], tb + TILE_B + offA[mt][ks]);
#pragma unroll
            for (int nt = 0; nt < 8; nt++)
#pragma unroll
                for (int mt = 0; mt < 2; mt++) mma16816(c[mt][nt], ax[mt], bx[nt]);
            // phase 3: Ah * Bl (overwrite bx)
#pragma unroll
            for (int np = 0; np < 4; np++) LDSM_X4(&bx[2 * np][0], tb + 3 * TILE_B + offB[np][ks]);
#pragma unroll
            for (int nt = 0; nt < 8; nt++)
#pragma unroll
                for (int mt = 0; mt < 2; mt++) mma16816(c[mt][nt], ah[mt], bx[nt]);
        }
        __syncthreads();
    }
#undef ISSUE

    // ---- epilogue: column-wise max/min/sum/sq over this warp's 32 rows ----
    float* s_mx = (float*)smem;            // [8][64]
    float* s_mn = s_mx + 512;
    float* s_sm = s_mn + 512;
    float* s_sq = s_sm + 512;

#pragma unroll
    for (int nt = 0; nt < 8; nt++) {
#pragma unroll
        for (int b = 0; b < 2; b++) {      // col = nt*8 + 2t + b; regs {b, b+2}
            float mx = fmaxf(fmaxf(c[0][nt][b], c[0][nt][b + 2]),
                             fmaxf(c[1][nt][b], c[1][nt][b + 2]));
            float mn = fminf(fminf(c[0][nt][b], c[0][nt][b + 2]),
                             fminf(c[1][nt][b], c[1][nt][b + 2]));
            float sm = c[0][nt][b] + c[0][nt][b + 2] + c[1][nt][b] + c[1][nt][b + 2];
            float sq = c[0][nt][b] * c[0][nt][b] + c[0][nt][b + 2] * c[0][nt][b + 2]
                     + c[1][nt][b] * c[1][nt][b] + c[1][nt][b + 2] * c[1][nt][b + 2];
#pragma unroll
            for (int o = 4; o < 32; o <<= 1) {
                mx = fmaxf(mx, __shfl_xor_sync(0xffffffffu, mx, o));
                mn = fminf(mn, __shfl_xor_sync(0xffffffffu, mn, o));
                sm += __shfl_xor_sync(0xffffffffu, sm, o);
                sq += __shfl_xor_sync(0xffffffffu, sq, o);
            }
            if (g == 0) {
                int cl = wid * 64 + (nt << 3) + 2 * t + b;
                s_mx[cl] = mx; s_mn[cl] = mn; s_sm[cl] = sm; s_sq[cl] = sq;
            }
        }
    }
    __syncthreads();

    {   // max/min per (jg, col): warp pair (wy = 2jg, 2jg+1) at wx = col>>6
        int jg = tid >> 7, col = tid & 127;
        int wxx = col >> 6, c64 = col & 63;
        int w0 = (wxx << 2) + (jg << 1);
        float mx = fmaxf(s_mx[w0 * 64 + c64], s_mx[(w0 + 1) * 64 + c64]);
        float mn = fminf(s_mn[w0 * 64 + c64], s_mn[(w0 + 1) * 64 + c64]);
        int si = si0 + jg;
        g_maxZ[(size_t)si * D2 + n0 + col] = mx;
        g_minZ[(size_t)si * D2 + n0 + col] = mn;
    }
    if (tid < 128) {   // BN2 partials over all 128 rows
        int col = tid, wxx = col >> 6, c64 = col & 63;
        float sm = 0.f, sq = 0.f;
#pragma unroll
        for (int w = 0; w < 4; w++) {
            sm += s_sm[((wxx << 2) + w) * 64 + c64];
            sq += s_sq[((wxx << 2) + w) * 64 + c64];
        }
        int s_ = si0 >> 6;
        atomicAdd(&g_sum2[s_ * D2 + n0 + col], sm);
        atomicAdd(&g_sq2 [s_ * D2 + n0 + col], sq);
    }
}

// ---------------- K6: finalize BN2 ----------------
__global__ void k_bn2(const float* __restrict__ g2, const float* __restrict__ be2) {
    int idx = blockIdx.x * 256 + threadIdx.x;
    if (idx >= SQ * D2) return;
    int d = idx & (D2 - 1);
    const float inv = 1.f / (float)PPRW;
    float m   = g_sum2[idx] * inv;
    float var = g_sq2[idx] * inv - m * m;
    float al  = g2[d] * rsqrtf(var + EPSV);
    g_ab2[idx] = make_float2(al, fmaf(-al, m, be2[d]));
}

// ---------------- K7: out ----------------
__global__ void k_out(float* __restrict__ out) {
    int idx = blockIdx.x * 256 + threadIdx.x;
    int si = idx >> 10;
    int d  = idx & (D2 - 1);
    int s  = si >> 6;
    float2 abv = g_ab2[s * D2 + d];
    float m = (abv.x >= 0.f) ? g_maxZ[idx] : g_minZ[idx];
    out[idx] = fmaxf(fmaf(abv.x, m, abv.y), 0.f);
}

// ---------------- launch ----------------
extern "C" void kernel_launch(void* const* d_in, const int* in_sizes, int n_in,
                              void* d_out, int out_size) {
    (void)in_sizes; (void)n_in; (void)out_size;
    const float* hs   = (const float*)d_in[0];
    const float* traj = (const float*)d_in[3];
    const float* tw   = (const float*)d_in[4];
    const float* Wsp  = (const float*)d_in[6];
    const float* bsp  = (const float*)d_in[7];
    const float* W1   = (const float*)d_in[8];
    const float* g1   = (const float*)d_in[10];
    const float* be1  = (const float*)d_in[11];
    const float* W2   = (const float*)d_in[12];
    const float* g2   = (const float*)d_in[14];
    const float* be2  = (const float*)d_in[15];
    float* out = (float*)d_out;

    cudaFuncSetAttribute(k_gemm2m, cudaFuncAttributeMaxDynamicSharedMemorySize, GT2_SMEM);

    k_zero <<<128, 256>>>();
    k_embed<<<NB, 128>>>(traj, Wsp, hs, W1);
    k_V    <<<4, 128>>>(bsp, W1);
    k_U    <<<NB / 8, 128>>>(W1);
    k_wconv<<<dim3(16, 32), dim3(32, 8)>>>(W2);
    k_p1   <<<dim3(4, 64, SQ), 128>>>(tw);
    k_p2   <<<dim3(4, 64, SQ), 128>>>(tw);
    k_bn1  <<<64, 256>>>(g1, be1);
    k_conv <<<65536, 256>>>();
    k_gemm2m<<<dim3(8, 1024), 256, GT2_SMEM>>>();
    k_bn2  <<<128, 256>>>(g2, be2);
    k_out  <<<8192, 256>>>(out);
}

// round 9
// speedup vs baseline: 1.9847x; 1.0311x over previous
#include <cuda_runtime.h>
#include <cuda_bf16.h>
#include <cstdint>
#include <cstddef>

// ---------------- problem constants ----------------
#define SQ   32
#define PP64 64
#define NB   2048
#define PPRW 4096
#define D1   512
#define D2   1024
#define NKAP 16
#define EPSV 1e-5f

// ---------------- scratch ----------------
__device__ __align__(256) float g_a  [NB * 512];
__device__ __align__(256) float g_hW [NB * 512];
__device__ __align__(256) float g_U  [NB * NKAP * 512];
__device__ __align__(256) float g_V  [NKAP * 512];
__device__ __align__(256) float g_Z1 [(size_t)NB * PP64 * 512];   // 268 MB
__device__ float  g_sum1[SQ * 512];
__device__ float  g_sq1 [SQ * 512];
__device__ float2 g_ab1 [SQ * 512];
__device__ float  g_sum2[SQ * D2];
__device__ float  g_sq2 [SQ * D2];
__device__ float2 g_ab2 [SQ * D2];
__device__ __align__(256) float g_maxZ[NB * D2];
__device__ __align__(256) float g_minZ[NB * D2];
// bf16 split operands for HMMA GEMM2
__device__ __align__(256) __nv_bfloat16 g_Ah[(size_t)NB * PP64 * 512];  // 134 MB
__device__ __align__(256) __nv_bfloat16 g_Al[(size_t)NB * PP64 * 512];  // 134 MB
__device__ __align__(256) __nv_bfloat16 g_Bh[(size_t)D2 * 512];         // W2^T hi
__device__ __align__(256) __nv_bfloat16 g_Bl[(size_t)D2 * 512];         // W2^T lo

__device__ __forceinline__ uint32_t smem_u32(const void* p) {
    uint32_t a;
    asm("{ .reg .u64 t; cvta.to.shared.u64 t, %1; cvt.u32.u64 %0, t; }" : "=r"(a) : "l"(p));
    return a;
}

// ---------------- K0: zero BN accumulators ----------------
__global__ void k_zero() {
    int i = blockIdx.x * blockDim.x + threadIdx.x;
    if (i < SQ * 512) { g_sum1[i] = 0.f; g_sq1[i] = 0.f; }
    if (i < SQ * D2)  { g_sum2[i] = 0.f; g_sq2[i] = 0.f; }
}

// ---------------- K1: a = obs @ W_sp ; hW = h @ W1[512:576,:] ----------------
__global__ void k_embed(const float* __restrict__ traj, const float* __restrict__ Wsp,
                        const float* __restrict__ hs,   const float* __restrict__ W1) {
    int b = blockIdx.x;
    int tid = threadIdx.x;
    __shared__ float obs[16];
    __shared__ float hsh[64];
    if (tid < 16) {
        int t = tid >> 1, c = tid & 1;
        obs[tid] = traj[((size_t)t * NB + b) * 2 + c];
    }
    if (tid < 64) hsh[tid] = hs[b * 64 + tid];
    __syncthreads();
#pragma unroll
    for (int q = 0; q < 4; q++) {
        int f = tid + 128 * q;
        float acc = 0.f;
#pragma unroll
        for (int r = 0; r < 16; r++) acc = fmaf(obs[r], Wsp[r * 512 + f], acc);
        g_a[b * 512 + f] = acc;
        float ah = 0.f;
#pragma unroll
        for (int k = 0; k < 64; k++) ah = fmaf(hsh[k], W1[(512 + k) * 512 + f], ah);
        g_hW[b * 512 + f] = ah;
    }
}

// ---------------- K1b: V[kap][d] ----------------
__global__ void k_V(const float* __restrict__ bsp, const float* __restrict__ W1) {
    int d = blockIdx.x * 128 + threadIdx.x;
#pragma unroll
    for (int kap = 0; kap < NKAP; kap++) {
        int par = kap >> 3, t = kap & 7;
        float acc = 0.f;
#pragma unroll 4
        for (int e = par; e < 64; e += 2) {
            int f = t * 64 + e;
            acc = fmaf(bsp[f], W1[f * 512 + d], acc);
        }
        g_V[kap * 512 + d] = acc;
    }
}

// ---------------- K2: U[b][kap][d]; 16 peds/block, kappa split x2 ----------------
__global__ void k_U(const float* __restrict__ W1) {
    int b0 = blockIdx.x * 16;           // 128 m-blocks
    int kap0 = blockIdx.y * 8;          // 2 kappa-blocks
    int d  = threadIdx.x;               // 512
    __shared__ float a[16][512];
    for (int idx = threadIdx.x; idx < 16 * 512; idx += 512)
        a[idx >> 9][idx & 511] = g_a[b0 * 512 + idx];
    __syncthreads();
#pragma unroll 1
    for (int kk = 0; kk < 8; kk++) {
        int kap = kap0 + kk;
        int par = kap >> 3, t = kap & 7;
        float acc[16];
#pragma unroll
        for (int bb = 0; bb < 16; bb++) acc[bb] = 0.f;
#pragma unroll 8
        for (int e = par; e < 64; e += 2) {
            int f = t * 64 + e;
            float w1 = W1[f * 512 + d];
#pragma unroll
            for (int bb = 0; bb < 16; bb++) acc[bb] = fmaf(a[bb][f], w1, acc[bb]);
        }
#pragma unroll
        for (int bb = 0; bb < 16; bb++)
            g_U[(size_t)((b0 + bb) * NKAP + kap) * 512 + d] = acc[bb];
    }
}

// ---------------- K2b: W2^T -> bf16 hi/lo ----------------
__global__ void k_wconv(const float* __restrict__ W2) {
    __shared__ float t[32][33];
    int k0 = blockIdx.x * 32, n0 = blockIdx.y * 32;
    int tx = threadIdx.x, ty = threadIdx.y;
#pragma unroll
    for (int r = 0; r < 32; r += 8)
        t[ty + r][tx] = W2[(size_t)(k0 + ty + r) * D2 + n0 + tx];
    __syncthreads();
#pragma unroll
    for (int r = 0; r < 32; r += 8) {
        float v = t[tx][ty + r];
        __nv_bfloat16 hi = __float2bfloat16(v);
        __nv_bfloat16 lo = __float2bfloat16(v - __bfloat162float(hi));
        size_t o = (size_t)(n0 + ty + r) * 512 + k0 + tx;
        g_Bh[o] = hi; g_Bl[o] = lo;
    }
}

// ---------------- K3a / K3b: Z1 build + BN1 stats ----------------
__global__ void k_p1(const float* __restrict__ tw) {
    int tid = threadIdx.x;
    int dt = blockIdx.x, j = blockIdx.y, s = blockIdx.z;
    int d  = (dt << 7) + tid;
    int bj = (s << 6) + j;
    __shared__ float wsh[64][16];
    for (int idx = tid; idx < 1024; idx += 128) {
        int i = idx >> 4, kap = idx & 15;
        wsh[i][kap] = tw[(size_t)((s << 12) + (i << 6) + j) * 16 + kap];
    }
    float uj[16];
#pragma unroll
    for (int kap = 0; kap < 16; kap++)
        uj[kap] = g_U[(size_t)((bj << 4) + kap) * 512 + d];
    float hwj = g_hW[bj * 512 + d];
    __syncthreads();
    float* zbase = g_Z1 + (size_t)((s << 12) + j) * 512 + d;
#pragma unroll 4
    for (int i = 0; i < 64; i++) {
        float acc = hwj;
#pragma unroll
        for (int kap = 0; kap < 16; kap++) acc = fmaf(wsh[i][kap], uj[kap], acc);
        zbase[(size_t)i * (64 * 512)] = acc;
    }
}

__global__ void k_p2(const float* __restrict__ tw) {
    int tid = threadIdx.x;
    int dt = blockIdx.x, i = blockIdx.y, s = blockIdx.z;
    int d  = (dt << 7) + tid;
    int bi = (s << 6) + i;
    __shared__ float wsh[64][16];
    for (int idx = tid; idx < 1024; idx += 128)
        ((float*)wsh)[idx] = tw[(size_t)((s << 12) + (i << 6)) * 16 + idx];
    float vu[16];
#pragma unroll
    for (int kap = 0; kap < 16; kap++)
        vu[kap] = g_V[(kap << 9) + d] - g_U[(size_t)((bi << 4) + kap) * 512 + d];
    __syncthreads();
    float lsum = 0.f, lsq = 0.f;
    float* zbase = g_Z1 + (size_t)((s << 12) + (i << 6)) * 512 + d;
#pragma unroll 4
    for (int j = 0; j < 64; j++) {
        float acc = 0.f;
#pragma unroll
        for (int kap = 0; kap < 16; kap++) acc = fmaf(wsh[j][kap], vu[kap], acc);
        float z = zbase[(size_t)j * 512] + acc;
        zbase[(size_t)j * 512] = z;
        lsum += z;
        lsq  = fmaf(z, z, lsq);
    }
    atomicAdd(&g_sum1[(s << 9) + d], lsum);
    atomicAdd(&g_sq1 [(s << 9) + d], lsq);
}

// ---------------- K4: finalize BN1 ----------------
__global__ void k_bn1(const float* __restrict__ g1, const float* __restrict__ be1) {
    int idx = blockIdx.x * 256 + threadIdx.x;
    if (idx >= SQ * 512) return;
    int d = idx & 511;
    const float inv = 1.f / (float)PPRW;
    float m   = g_sum1[idx] * inv;
    float var = g_sq1[idx] * inv - m * m;
    float al  = g1[d] * rsqrtf(var + EPSV);
    g_ab1[idx] = make_float2(al, fmaf(-al, m, be1[d]));
}

// ---------------- K4b: A1 = relu(bn1(Z1)) -> bf16 hi/lo split ----------------
__global__ void k_conv() {
    size_t idx = ((size_t)blockIdx.x * 256 + threadIdx.x) * 4;
    float4 z = *(const float4*)(g_Z1 + idx);
    int d = (int)(idx & 511);
    int s = (int)(idx >> 21);
    const float2* abp = g_ab1 + (s << 9) + d;
    float v[4] = {z.x, z.y, z.z, z.w};
    __nv_bfloat16 hi[4], lo[4];
#pragma unroll
    for (int q = 0; q < 4; q++) {
        float2 ab = abp[q];
        float a1 = fmaxf(fmaf(ab.x, v[q], ab.y), 0.f);
        hi[q] = __float2bfloat16(a1);
        lo[q] = __float2bfloat16(a1 - __bfloat162float(hi[q]));
    }
    __nv_bfloat162* ph = (__nv_bfloat162*)(g_Ah + idx);
    __nv_bfloat162* pl = (__nv_bfloat162*)(g_Al + idx);
    ph[0] = __nv_bfloat162(hi[0], hi[1]); ph[1] = __nv_bfloat162(hi[2], hi[3]);
    pl[0] = __nv_bfloat162(lo[0], lo[1]); pl[1] = __nv_bfloat162(lo[2], lo[3]);
}

// ---------------- K5: HMMA bf16 split GEMM2 (ldmatrix + phased terms) -------
#define BK     32
#define APITCH 40
#define TILE_B (128 * APITCH * 2)
#define BUF_B  (4 * TILE_B)
#define GT2_SMEM (2 * BUF_B)

__device__ __forceinline__ void mma16816(float* c, const uint32_t* a, const uint32_t* b) {
    asm volatile("mma.sync.aligned.m16n8k16.row.col.f32.bf16.bf16.f32 "
                 "{%0,%1,%2,%3}, {%4,%5,%6,%7}, {%8,%9}, {%0,%1,%2,%3};"
                 : "+f"(c[0]), "+f"(c[1]), "+f"(c[2]), "+f"(c[3])
                 : "r"(a[0]), "r"(a[1]), "r"(a[2]), "r"(a[3]), "r"(b[0]), "r"(b[1]));
}
#define LDSM_X4(r, addr) \
    asm volatile("ldmatrix.sync.aligned.m8n8.x4.shared.b16 {%0,%1,%2,%3}, [%4];" \
        : "=r"((r)[0]), "=r"((r)[1]), "=r"((r)[2]), "=r"((r)[3]) : "r"(addr))

__global__ void __launch_bounds__(256, 2) k_gemm2m() {
    extern __shared__ __align__(16) char smem[];
    const uint32_t sb = smem_u32(smem);
    const int tid  = threadIdx.x;
    const int wid  = tid >> 5;
    const int lane = tid & 31;
    const int wy   = wid & 3;
    const int wx   = wid >> 2;
    const int g    = lane >> 2;
    const int t    = lane & 3;
    const int nblk = blockIdx.x;
    const int mblk = blockIdx.y;
    const int n0   = nblk << 7;
    const size_t arow0 = (size_t)mblk << 7;
    const int si0  = mblk << 1;

    const int mrow  = ((lane >> 3) & 1) * 8 + (lane & 7);
    const int kselA = (lane >> 4) << 3;
    const int browB = ((lane >> 4) << 3) + (lane & 7);
    const int kselB = ((lane >> 3) & 1) << 3;
    uint32_t offA[2][2], offB[4][2];
#pragma unroll
    for (int mt = 0; mt < 2; mt++)
#pragma unroll
        for (int ks = 0; ks < 2; ks++)
            offA[mt][ks] = (uint32_t)(((wy * 32 + mt * 16 + mrow) * APITCH + ks * 16 + kselA) * 2);
#pragma unroll
    for (int np = 0; np < 4; np++)
#pragma unroll
        for (int ks = 0; ks < 2; ks++)
            offB[np][ks] = (uint32_t)(((wx * 64 + np * 16 + browB) * APITCH + ks * 16 + kselB) * 2);

    float c[2][8][4];
#pragma unroll
    for (int mt = 0; mt < 2; mt++)
#pragma unroll
        for (int nt = 0; nt < 8; nt++)
#pragma unroll
            for (int r = 0; r < 4; r++) c[mt][nt][r] = 0.f;

#define ISSUE(c_, buf_) do {                                                   \
    int _k0 = (c_) << 5;                                                       \
    char* _bb = smem + (buf_) * BUF_B;                                         \
    _Pragma("unroll")                                                          \
    for (int _q = 0; _q < 8; _q++) {                                           \
        int _seg = tid + (_q << 8);                                            \
        int _tile = _seg >> 9;                                                 \
        int _r = (_seg >> 2) & 127;                                            \
        int _qq = _seg & 3;                                                    \
        const __nv_bfloat16* _src;                                             \
        if (_tile == 0)      _src = g_Ah + ((arow0 + _r) << 9) + _k0 + (_qq << 3); \
        else if (_tile == 1) _src = g_Al + ((arow0 + _r) << 9) + _k0 + (_qq << 3); \
        else if (_tile == 2) _src = g_Bh + ((size_t)(n0 + _r) << 9) + _k0 + (_qq << 3); \
        else                 _src = g_Bl + ((size_t)(n0 + _r) << 9) + _k0 + (_qq << 3); \
        uint32_t _dst;                                                         \
        asm("{ .reg .u64 t; cvta.to.shared.u64 t, %1; cvt.u32.u64 %0, t; }"    \
            : "=r"(_dst) : "l"(_bb + _tile * TILE_B + _r * (APITCH * 2) + (_qq << 4))); \
        asm volatile("cp.async.cg.shared.global [%0], [%1], 16;"               \
                     :: "r"(_dst), "l"(_src));                                 \
    }                                                                          \
    asm volatile("cp.async.commit_group;" ::: "memory");                       \
} while (0)

    ISSUE(0, 0);

    for (int ch = 0; ch < 16; ch++) {
        const int buf = ch & 1;
        if (ch < 15) {
            ISSUE(ch + 1, buf ^ 1);
            asm volatile("cp.async.wait_group 1;" ::: "memory");
        } else {
            asm volatile("cp.async.wait_group 0;" ::: "memory");
        }
        __syncthreads();

        const uint32_t tb = sb + buf * BUF_B;
#pragma unroll
        for (int ks = 0; ks < 2; ks++) {
            uint32_t ah[2][4], ax[2][4], bx[8][2];
            // phase 1: Ah * Bh
#pragma unroll
            for (int mt = 0; mt < 2; mt++) LDSM_X4(ah[mt], tb + offA[mt][ks]);
#pragma unroll
            for (int np = 0; np < 4; np++) LDSM_X4(&bx[2 * np][0], tb + 2 * TILE_B + offB[np][ks]);
#pragma unroll
            for (int nt = 0; nt < 8; nt++)
#pragma unroll
                for (int mt = 0; mt < 2; mt++) mma16816(c[mt][nt], ah[mt], bx[nt]);
            // phase 2: Al * Bh
#pragma unroll
            for (int mt = 0; mt < 2; mt++) LDSM_X4(ax[mt], tb + TILE_B + offA[mt][ks]);
#pragma unroll
            for (int nt = 0; nt < 8; nt++)
#pragma unroll
                for (int mt = 0; mt < 2; mt++) mma16816(c[mt][nt], ax[mt], bx[nt]);
            // phase 3: Ah * Bl (overwrite bx)
#pragma unroll
            for (int np = 0; np < 4; np++) LDSM_X4(&bx[2 * np][0], tb + 3 * TILE_B + offB[np][ks]);
#pragma unroll
            for (int nt = 0; nt < 8; nt++)
#pragma unroll
                for (int mt = 0; mt < 2; mt++) mma16816(c[mt][nt], ah[mt], bx[nt]);
        }
        __syncthreads();
    }
#undef ISSUE

    // ---- epilogue ----
    float* s_mx = (float*)smem;            // [8][64]
    float* s_mn = s_mx + 512;
    float* s_sm = s_mn + 512;
    float* s_sq = s_sm + 512;

#pragma unroll
    for (int nt = 0; nt < 8; nt++) {
#pragma unroll
        for (int b = 0; b < 2; b++) {
            float mx = fmaxf(fmaxf(c[0][nt][b], c[0][nt][b + 2]),
                             fmaxf(c[1][nt][b], c[1][nt][b + 2]));
            float mn = fminf(fminf(c[0][nt][b], c[0][nt][b + 2]),
                             fminf(c[1][nt][b], c[1][nt][b + 2]));
            float sm = c[0][nt][b] + c[0][nt][b + 2] + c[1][nt][b] + c[1][nt][b + 2];
            float sq = c[0][nt][b] * c[0][nt][b] + c[0][nt][b + 2] * c[0][nt][b + 2]
                     + c[1][nt][b] * c[1][nt][b] + c[1][nt][b + 2] * c[1][nt][b + 2];
#pragma unroll
            for (int o = 4; o < 32; o <<= 1) {
                mx = fmaxf(mx, __shfl_xor_sync(0xffffffffu, mx, o));
                mn = fminf(mn, __shfl_xor_sync(0xffffffffu, mn, o));
                sm += __shfl_xor_sync(0xffffffffu, sm, o);
                sq += __shfl_xor_sync(0xffffffffu, sq, o);
            }
            if (g == 0) {
                int cl = wid * 64 + (nt << 3) + 2 * t + b;
                s_mx[cl] = mx; s_mn[cl] = mn; s_sm[cl] = sm; s_sq[cl] = sq;
            }
        }
    }
    __syncthreads();

    {
        int jg = tid >> 7, col = tid & 127;
        int wxx = col >> 6, c64 = col & 63;
        int w0 = (wxx << 2) + (jg << 1);
        float mx = fmaxf(s_mx[w0 * 64 + c64], s_mx[(w0 + 1) * 64 + c64]);
        float mn = fminf(s_mn[w0 * 64 + c64], s_mn[(w0 + 1) * 64 + c64]);
        int si = si0 + jg;
        g_maxZ[(size_t)si * D2 + n0 + col] = mx;
        g_minZ[(size_t)si * D2 + n0 + col] = mn;
    }
    if (tid < 128) {
        int col = tid, wxx = col >> 6, c64 = col & 63;
        float sm = 0.f, sq = 0.f;
#pragma unroll
        for (int w = 0; w < 4; w++) {
            sm += s_sm[((wxx << 2) + w) * 64 + c64];
            sq += s_sq[((wxx << 2) + w) * 64 + c64];
        }
        int s_ = si0 >> 6;
        atomicAdd(&g_sum2[s_ * D2 + n0 + col], sm);
        atomicAdd(&g_sq2 [s_ * D2 + n0 + col], sq);
    }
}

// ---------------- K6: finalize BN2 ----------------
__global__ void k_bn2(const float* __restrict__ g2, const float* __restrict__ be2) {
    int idx = blockIdx.x * 256 + threadIdx.x;
    if (idx >= SQ * D2) return;
    int d = idx & (D2 - 1);
    const float inv = 1.f / (float)PPRW;
    float m   = g_sum2[idx] * inv;
    float var = g_sq2[idx] * inv - m * m;
    float al  = g2[d] * rsqrtf(var + EPSV);
    g_ab2[idx] = make_float2(al, fmaf(-al, m, be2[d]));
}

// ---------------- K7: out ----------------
__global__ void k_out(float* __restrict__ out) {
    int idx = blockIdx.x * 256 + threadIdx.x;
    int si = idx >> 10;
    int d  = idx & (D2 - 1);
    int s  = si >> 6;
    float2 abv = g_ab2[s * D2 + d];
    float m = (abv.x >= 0.f) ? g_maxZ[idx] : g_minZ[idx];
    out[idx] = fmaxf(fmaf(abv.x, m, abv.y), 0.f);
}

// ---------------- launch ----------------
extern "C" void kernel_launch(void* const* d_in, const int* in_sizes, int n_in,
                              void* d_out, int out_size) {
    (void)in_sizes; (void)n_in; (void)out_size;
    const float* hs   = (const float*)d_in[0];
    const float* traj = (const float*)d_in[3];
    const float* tw   = (const float*)d_in[4];
    const float* Wsp  = (const float*)d_in[6];
    const float* bsp  = (const float*)d_in[7];
    const float* W1   = (const float*)d_in[8];
    const float* g1   = (const float*)d_in[10];
    const float* be1  = (const float*)d_in[11];
    const float* W2   = (const float*)d_in[12];
    const float* g2   = (const float*)d_in[14];
    const float* be2  = (const float*)d_in[15];
    float* out = (float*)d_out;

    cudaFuncSetAttribute(k_gemm2m, cudaFuncAttributeMaxDynamicSharedMemorySize, GT2_SMEM);

    k_zero <<<128, 256>>>();
    k_embed<<<NB, 128>>>(traj, Wsp, hs, W1);
    k_V    <<<4, 128>>>(bsp, W1);
    k_U    <<<dim3(NB / 16, 2), 512>>>(W1);
    k_wconv<<<dim3(16, 32), dim3(32, 8)>>>(W2);
    k_p1   <<<dim3(4, 64, SQ), 128>>>(tw);
    k_p2   <<<dim3(4, 64, SQ), 128>>>(tw);
    k_bn1  <<<64, 256>>>(g1, be1);
    k_conv <<<65536, 256>>>();
    k_gemm2m<<<dim3(8, 1024), 256, GT2_SMEM>>>();
    k_bn2  <<<128, 256>>>(g2, be2);
    k_out  <<<8192, 256>>>(out);
}

// round 10
// speedup vs baseline: 2.5353x; 1.2774x over previous
#include <cuda_runtime.h>
#include <cuda_bf16.h>
#include <cuda_fp16.h>
#include <cstdint>
#include <cstddef>

// ---------------- problem constants ----------------
#define SQ   32
#define PP64 64
#define NB   2048
#define PPRW 4096
#define D1   512
#define D2   1024
#define NKAP 16
#define EPSV 1e-5f

// ---------------- scratch ----------------
__device__ __align__(256) float g_a  [NB * 512];
__device__ __align__(256) float g_hW [NB * 512];
__device__ __align__(256) float g_U  [NB * NKAP * 512];
__device__ __align__(256) float g_V  [NKAP * 512];
__device__ __align__(256) float g_Z1 [(size_t)NB * PP64 * 512];   // 268 MB
__device__ float  g_sum1[SQ * 512];
__device__ float  g_sq1 [SQ * 512];
__device__ float2 g_ab1 [SQ * 512];
__device__ float  g_sum2[SQ * D2];
__device__ float  g_sq2 [SQ * D2];
__device__ float2 g_ab2 [SQ * D2];
__device__ __align__(256) float g_maxZ[NB * D2];
__device__ __align__(256) float g_minZ[NB * D2];
// fp16 split operands for HMMA GEMM2 (A = Ah + Al exact to ~2^-22; B single fp16)
__device__ __align__(256) __half g_Ah[(size_t)NB * PP64 * 512];   // 134 MB
__device__ __align__(256) __half g_Al[(size_t)NB * PP64 * 512];   // 134 MB
__device__ __align__(256) __half g_Bh[(size_t)D2 * 512];          // W2^T fp16

__device__ __forceinline__ uint32_t smem_u32(const void* p) {
    uint32_t a;
    asm("{ .reg .u64 t; cvta.to.shared.u64 t, %1; cvt.u32.u64 %0, t; }" : "=r"(a) : "l"(p));
    return a;
}

// ---------------- K0: zero BN accumulators ----------------
__global__ void k_zero() {
    int i = blockIdx.x * blockDim.x + threadIdx.x;
    if (i < SQ * 512) { g_sum1[i] = 0.f; g_sq1[i] = 0.f; }
    if (i < SQ * D2)  { g_sum2[i] = 0.f; g_sq2[i] = 0.f; }
}

// ---------------- K1: a = obs @ W_sp ; hW = h @ W1[512:576,:] ----------------
__global__ void k_embed(const float* __restrict__ traj, const float* __restrict__ Wsp,
                        const float* __restrict__ hs,   const float* __restrict__ W1) {
    int b = blockIdx.x;
    int tid = threadIdx.x;
    __shared__ float obs[16];
    __shared__ float hsh[64];
    if (tid < 16) {
        int t = tid >> 1, c = tid & 1;
        obs[tid] = traj[((size_t)t * NB + b) * 2 + c];
    }
    if (tid < 64) hsh[tid] = hs[b * 64 + tid];
    __syncthreads();
#pragma unroll
    for (int q = 0; q < 4; q++) {
        int f = tid + 128 * q;
        float acc = 0.f;
#pragma unroll
        for (int r = 0; r < 16; r++) acc = fmaf(obs[r], Wsp[r * 512 + f], acc);
        g_a[b * 512 + f] = acc;
        float ah = 0.f;
#pragma unroll
        for (int k = 0; k < 64; k++) ah = fmaf(hsh[k], W1[(512 + k) * 512 + f], ah);
        g_hW[b * 512 + f] = ah;
    }
}

// ---------------- K1b: V[kap][d] ----------------
__global__ void k_V(const float* __restrict__ bsp, const float* __restrict__ W1) {
    int d = blockIdx.x * 128 + threadIdx.x;
#pragma unroll
    for (int kap = 0; kap < NKAP; kap++) {
        int par = kap >> 3, t = kap & 7;
        float acc = 0.f;
#pragma unroll 4
        for (int e = par; e < 64; e += 2) {
            int f = t * 64 + e;
            acc = fmaf(bsp[f], W1[f * 512 + d], acc);
        }
        g_V[kap * 512 + d] = acc;
    }
}

// ---------------- K2: U[b][kap][d]; 16 peds/block, kappa split x2 ----------------
__global__ void k_U(const float* __restrict__ W1) {
    int b0 = blockIdx.x * 16;
    int kap0 = blockIdx.y * 8;
    int d  = threadIdx.x;
    __shared__ float a[16][512];
    for (int idx = threadIdx.x; idx < 16 * 512; idx += 512)
        a[idx >> 9][idx & 511] = g_a[b0 * 512 + idx];
    __syncthreads();
#pragma unroll 1
    for (int kk = 0; kk < 8; kk++) {
        int kap = kap0 + kk;
        int par = kap >> 3, t = kap & 7;
        float acc[16];
#pragma unroll
        for (int bb = 0; bb < 16; bb++) acc[bb] = 0.f;
#pragma unroll 8
        for (int e = par; e < 64; e += 2) {
            int f = t * 64 + e;
            float w1 = W1[f * 512 + d];
#pragma unroll
            for (int bb = 0; bb < 16; bb++) acc[bb] = fmaf(a[bb][f], w1, acc[bb]);
        }
#pragma unroll
        for (int bb = 0; bb < 16; bb++)
            g_U[(size_t)((b0 + bb) * NKAP + kap) * 512 + d] = acc[bb];
    }
}

// ---------------- K2b: W2^T -> fp16 ----------------
__global__ void k_wconv(const float* __restrict__ W2) {
    __shared__ float t[32][33];
    int k0 = blockIdx.x * 32, n0 = blockIdx.y * 32;
    int tx = threadIdx.x, ty = threadIdx.y;
#pragma unroll
    for (int r = 0; r < 32; r += 8)
        t[ty + r][tx] = W2[(size_t)(k0 + ty + r) * D2 + n0 + tx];
    __syncthreads();
#pragma unroll
    for (int r = 0; r < 32; r += 8) {
        float v = t[tx][ty + r];
        g_Bh[(size_t)(n0 + ty + r) * 512 + k0 + tx] = __float2half_rn(v);
    }
}

// ---------------- K3a / K3b: Z1 build + BN1 stats ----------------
__global__ void k_p1(const float* __restrict__ tw) {
    int tid = threadIdx.x;
    int dt = blockIdx.x, j = blockIdx.y, s = blockIdx.z;
    int d  = (dt << 7) + tid;
    int bj = (s << 6) + j;
    __shared__ float wsh[64][16];
    for (int idx = tid; idx < 1024; idx += 128) {
        int i = idx >> 4, kap = idx & 15;
        wsh[i][kap] = tw[(size_t)((s << 12) + (i << 6) + j) * 16 + kap];
    }
    float uj[16];
#pragma unroll
    for (int kap = 0; kap < 16; kap++)
        uj[kap] = g_U[(size_t)((bj << 4) + kap) * 512 + d];
    float hwj = g_hW[bj * 512 + d];
    __syncthreads();
    float* zbase = g_Z1 + (size_t)((s << 12) + j) * 512 + d;
#pragma unroll 4
    for (int i = 0; i < 64; i++) {
        float acc = hwj;
#pragma unroll
        for (int kap = 0; kap < 16; kap++) acc = fmaf(wsh[i][kap], uj[kap], acc);
        zbase[(size_t)i * (64 * 512)] = acc;
    }
}

__global__ void k_p2(const float* __restrict__ tw) {
    int tid = threadIdx.x;
    int dt = blockIdx.x, i = blockIdx.y, s = blockIdx.z;
    int d  = (dt << 7) + tid;
    int bi = (s << 6) + i;
    __shared__ float wsh[64][16];
    for (int idx = tid; idx < 1024; idx += 128)
        ((float*)wsh)[idx] = tw[(size_t)((s << 12) + (i << 6)) * 16 + idx];
    float vu[16];
#pragma unroll
    for (int kap = 0; kap < 16; kap++)
        vu[kap] = g_V[(kap << 9) + d] - g_U[(size_t)((bi << 4) + kap) * 512 + d];
    __syncthreads();
    float lsum = 0.f, lsq = 0.f;
    float* zbase = g_Z1 + (size_t)((s << 12) + (i << 6)) * 512 + d;
#pragma unroll 4
    for (int j = 0; j < 64; j++) {
        float acc = 0.f;
#pragma unroll
        for (int kap = 0; kap < 16; kap++) acc = fmaf(wsh[j][kap], vu[kap], acc);
        float z = zbase[(size_t)j * 512] + acc;
        zbase[(size_t)j * 512] = z;
        lsum += z;
        lsq  = fmaf(z, z, lsq);
    }
    atomicAdd(&g_sum1[(s << 9) + d], lsum);
    atomicAdd(&g_sq1 [(s << 9) + d], lsq);
}

// ---------------- K4: finalize BN1 ----------------
__global__ void k_bn1(const float* __restrict__ g1, const float* __restrict__ be1) {
    int idx = blockIdx.x * 256 + threadIdx.x;
    if (idx >= SQ * 512) return;
    int d = idx & 511;
    const float inv = 1.f / (float)PPRW;
    float m   = g_sum1[idx] * inv;
    float var = g_sq1[idx] * inv - m * m;
    float al  = g1[d] * rsqrtf(var + EPSV);
    g_ab1[idx] = make_float2(al, fmaf(-al, m, be1[d]));
}

// ---------------- K4b: A1 = relu(bn1(Z1)) -> fp16 hi/lo split ----------------
__global__ void k_conv() {
    size_t idx = ((size_t)blockIdx.x * 256 + threadIdx.x) * 4;
    float4 z = *(const float4*)(g_Z1 + idx);
    int d = (int)(idx & 511);
    int s = (int)(idx >> 21);
    const float2* abp = g_ab1 + (s << 9) + d;
    float v[4] = {z.x, z.y, z.z, z.w};
    __half hi[4], lo[4];
#pragma unroll
    for (int q = 0; q < 4; q++) {
        float2 ab = abp[q];
        float a1 = fmaxf(fmaf(ab.x, v[q], ab.y), 0.f);
        hi[q] = __float2half_rn(a1);
        lo[q] = __float2half_rn(a1 - __half2float(hi[q]));
    }
    __half2* ph = (__half2*)(g_Ah + idx);
    __half2* pl = (__half2*)(g_Al + idx);
    ph[0] = __halves2half2(hi[0], hi[1]); ph[1] = __halves2half2(hi[2], hi[3]);
    pl[0] = __halves2half2(lo[0], lo[1]); pl[1] = __halves2half2(lo[2], lo[3]);
}

// ---------------- K5: HMMA fp16 2-term split GEMM2 --------------------------
// CTA: M=128 (2 si x 64 j), N=128, K=512 (BK=32). Z2 = (Ah+Al) @ Bh^T.
#define BK     32
#define APITCH 40                       // fp16 elems per smem row (bank-perm)
#define TILE_B (128 * APITCH * 2)       // 10240 B per operand tile
#define BUF_B  (3 * TILE_B)             // Ah, Al, Bh = 30720 B
#define GT2_SMEM (2 * BUF_B)            // 61440 B

__device__ __forceinline__ void mma16816(float* c, const uint32_t* a, const uint32_t* b) {
    asm volatile("mma.sync.aligned.m16n8k16.row.col.f32.f16.f16.f32 "
                 "{%0,%1,%2,%3}, {%4,%5,%6,%7}, {%8,%9}, {%0,%1,%2,%3};"
                 : "+f"(c[0]), "+f"(c[1]), "+f"(c[2]), "+f"(c[3])
                 : "r"(a[0]), "r"(a[1]), "r"(a[2]), "r"(a[3]), "r"(b[0]), "r"(b[1]));
}
#define LDSM_X4(r, addr) \
    asm volatile("ldmatrix.sync.aligned.m8n8.x4.shared.b16 {%0,%1,%2,%3}, [%4];" \
        : "=r"((r)[0]), "=r"((r)[1]), "=r"((r)[2]), "=r"((r)[3]) : "r"(addr))

__global__ void __launch_bounds__(256, 2) k_gemm2m() {
    extern __shared__ __align__(16) char smem[];
    const uint32_t sb = smem_u32(smem);
    const int tid  = threadIdx.x;
    const int wid  = tid >> 5;
    const int lane = tid & 31;
    const int wy   = wid & 3;
    const int wx   = wid >> 2;
    const int g    = lane >> 2;
    const int t    = lane & 3;
    const int nblk = blockIdx.x;
    const int mblk = blockIdx.y;
    const int n0   = nblk << 7;
    const size_t arow0 = (size_t)mblk << 7;
    const int si0  = mblk << 1;

    const int mrow  = ((lane >> 3) & 1) * 8 + (lane & 7);
    const int kselA = (lane >> 4) << 3;
    const int browB = ((lane >> 4) << 3) + (lane & 7);
    const int kselB = ((lane >> 3) & 1) << 3;
    uint32_t offA[2][2], offB[4][2];
#pragma unroll
    for (int mt = 0; mt < 2; mt++)
#pragma unroll
        for (int ks = 0; ks < 2; ks++)
            offA[mt][ks] = (uint32_t)(((wy * 32 + mt * 16 + mrow) * APITCH + ks * 16 + kselA) * 2);
#pragma unroll
    for (int np = 0; np < 4; np++)
#pragma unroll
        for (int ks = 0; ks < 2; ks++)
            offB[np][ks] = (uint32_t)(((wx * 64 + np * 16 + browB) * APITCH + ks * 16 + kselB) * 2);

    float c[2][8][4];
#pragma unroll
    for (int mt = 0; mt < 2; mt++)
#pragma unroll
        for (int nt = 0; nt < 8; nt++)
#pragma unroll
            for (int r = 0; r < 4; r++) c[mt][nt][r] = 0.f;

    // 3 tiles x 512 16B-segments = 1536 = 256 threads x 6
#define ISSUE(c_, buf_) do {                                                   \
    int _k0 = (c_) << 5;                                                       \
    char* _bb = smem + (buf_) * BUF_B;                                         \
    _Pragma("unroll")                                                          \
    for (int _q = 0; _q < 6; _q++) {                                           \
        int _seg = tid + (_q << 8);                                            \
        int _tile = _seg >> 9;                                                 \
        int _r = (_seg >> 2) & 127;                                            \
        int _qq = _seg & 3;                                                    \
        const __half* _src;                                                    \
        if (_tile == 0)      _src = g_Ah + ((arow0 + _r) << 9) + _k0 + (_qq << 3); \
        else if (_tile == 1) _src = g_Al + ((arow0 + _r) << 9) + _k0 + (_qq << 3); \
        else                 _src = g_Bh + ((size_t)(n0 + _r) << 9) + _k0 + (_qq << 3); \
        uint32_t _dst;                                                         \
        asm("{ .reg .u64 t; cvta.to.shared.u64 t, %1; cvt.u32.u64 %0, t; }"    \
            : "=r"(_dst) : "l"(_bb + _tile * TILE_B + _r * (APITCH * 2) + (_qq << 4))); \
        asm volatile("cp.async.cg.shared.global [%0], [%1], 16;"               \
                     :: "r"(_dst), "l"(_src));                                 \
    }                                                                          \
    asm volatile("cp.async.commit_group;" ::: "memory");                       \
} while (0)

    ISSUE(0, 0);

    for (int ch = 0; ch < 16; ch++) {
        const int buf = ch & 1;
        if (ch < 15) {
            ISSUE(ch + 1, buf ^ 1);
            asm volatile("cp.async.wait_group 1;" ::: "memory");
        } else {
            asm volatile("cp.async.wait_group 0;" ::: "memory");
        }
        __syncthreads();

        const uint32_t tb = sb + buf * BUF_B;
#pragma unroll
        for (int ks = 0; ks < 2; ks++) {
            uint32_t ax[2][4], bx[8][2];
            // phase 1: Ah * Bh
#pragma unroll
            for (int mt = 0; mt < 2; mt++) LDSM_X4(ax[mt], tb + offA[mt][ks]);
#pragma unroll
            for (int np = 0; np < 4; np++) LDSM_X4(&bx[2 * np][0], tb + 2 * TILE_B + offB[np][ks]);
#pragma unroll
            for (int nt = 0; nt < 8; nt++)
#pragma unroll
                for (int mt = 0; mt < 2; mt++) mma16816(c[mt][nt], ax[mt], bx[nt]);
            // phase 2: Al * Bh (reuse bx)
#pragma unroll
            for (int mt = 0; mt < 2; mt++) LDSM_X4(ax[mt], tb + TILE_B + offA[mt][ks]);
#pragma unroll
            for (int nt = 0; nt < 8; nt++)
#pragma unroll
                for (int mt = 0; mt < 2; mt++) mma16816(c[mt][nt], ax[mt], bx[nt]);
        }
        __syncthreads();
    }
#undef ISSUE

    // ---- epilogue: column-wise max/min/sum/sq over this warp's 32 rows ----
    float* s_mx = (float*)smem;            // [8][64]
    float* s_mn = s_mx + 512;
    float* s_sm = s_mn + 512;
    float* s_sq = s_sm + 512;

#pragma unroll
    for (int nt = 0; nt < 8; nt++) {
#pragma unroll
        for (int b = 0; b < 2; b++) {
            float mx = fmaxf(fmaxf(c[0][nt][b], c[0][nt][b + 2]),
                             fmaxf(c[1][nt][b], c[1][nt][b + 2]));
            float mn = fminf(fminf(c[0][nt][b], c[0][nt][b + 2]),
                             fminf(c[1][nt][b], c[1][nt][b + 2]));
            float sm = c[0][nt][b] + c[0][nt][b + 2] + c[1][nt][b] + c[1][nt][b + 2];
            float sq = c[0][nt][b] * c[0][nt][b] + c[0][nt][b + 2] * c[0][nt][b + 2]
                     + c[1][nt][b] * c[1][nt][b] + c[1][nt][b + 2] * c[1][nt][b + 2];
#pragma unroll
            for (int o = 4; o < 32; o <<= 1) {
                mx = fmaxf(mx, __shfl_xor_sync(0xffffffffu, mx, o));
                mn = fminf(mn, __shfl_xor_sync(0xffffffffu, mn, o));
                sm += __shfl_xor_sync(0xffffffffu, sm, o);
                sq += __shfl_xor_sync(0xffffffffu, sq, o);
            }
            if (g == 0) {
                int cl = wid * 64 + (nt << 3) + 2 * t + b;
                s_mx[cl] = mx; s_mn[cl] = mn; s_sm[cl] = sm; s_sq[cl] = sq;
            }
        }
    }
    __syncthreads();

    {
        int jg = tid >> 7, col = tid & 127;
        int wxx = col >> 6, c64 = col & 63;
        int w0 = (wxx << 2) + (jg << 1);
        float mx = fmaxf(s_mx[w0 * 64 + c64], s_mx[(w0 + 1) * 64 + c64]);
        float mn = fminf(s_mn[w0 * 64 + c64], s_mn[(w0 + 1) * 64 + c64]);
        int si = si0 + jg;
        g_maxZ[(size_t)si * D2 + n0 + col] = mx;
        g_minZ[(size_t)si * D2 + n0 + col] = mn;
    }
    if (tid < 128) {
        int col = tid, wxx = col >> 6, c64 = col & 63;
        float sm = 0.f, sq = 0.f;
#pragma unroll
        for (int w = 0; w < 4; w++) {
            sm += s_sm[((wxx << 2) + w) * 64 + c64];
            sq += s_sq[((wxx << 2) + w) * 64 + c64];
        }
        int s_ = si0 >> 6;
        atomicAdd(&g_sum2[s_ * D2 + n0 + col], sm);
        atomicAdd(&g_sq2 [s_ * D2 + n0 + col], sq);
    }
}

// ---------------- K6: finalize BN2 ----------------
__global__ void k_bn2(const float* __restrict__ g2, const float* __restrict__ be2) {
    int idx = blockIdx.x * 256 + threadIdx.x;
    if (idx >= SQ * D2) return;
    int d = idx & (D2 - 1);
    const float inv = 1.f / (float)PPRW;
    float m   = g_sum2[idx] * inv;
    float var = g_sq2[idx] * inv - m * m;
    float al  = g2[d] * rsqrtf(var + EPSV);
    g_ab2[idx] = make_float2(al, fmaf(-al, m, be2[d]));
}

// ---------------- K7: out ----------------
__global__ void k_out(float* __restrict__ out) {
    int idx = blockIdx.x * 256 + threadIdx.x;
    int si = idx >> 10;
    int d  = idx & (D2 - 1);
    int s  = si >> 6;
    float2 abv = g_ab2[s * D2 + d];
    float m = (abv.x >= 0.f) ? g_maxZ[idx] : g_minZ[idx];
    out[idx] = fmaxf(fmaf(abv.x, m, abv.y), 0.f);
}

// ---------------- launch ----------------
extern "C" void kernel_launch(void* const* d_in, const int* in_sizes, int n_in,
                              void* d_out, int out_size) {
    (void)in_sizes; (void)n_in; (void)out_size;
    const float* hs   = (const float*)d_in[0];
    const float* traj = (const float*)d_in[3];
    const float* tw   = (const float*)d_in[4];
    const float* Wsp  = (const float*)d_in[6];
    const float* bsp  = (const float*)d_in[7];
    const float* W1   = (const float*)d_in[8];
    const float* g1   = (const float*)d_in[10];
    const float* be1  = (const float*)d_in[11];
    const float* W2   = (const float*)d_in[12];
    const float* g2   = (const float*)d_in[14];
    const float* be2  = (const float*)d_in[15];
    float* out = (float*)d_out;

    cudaFuncSetAttribute(k_gemm2m, cudaFuncAttributeMaxDynamicSharedMemorySize, GT2_SMEM);

    k_zero <<<128, 256>>>();
    k_embed<<<NB, 128>>>(traj, Wsp, hs, W1);
    k_V    <<<4, 128>>>(bsp, W1);
    k_U    <<<dim3(NB / 16, 2), 512>>>(W1);
    k_wconv<<<dim3(16, 32), dim3(32, 8)>>>(W2);
    k_p1   <<<dim3(4, 64, SQ), 128>>>(tw);
    k_p2   <<<dim3(4, 64, SQ), 128>>>(tw);
    k_bn1  <<<64, 256>>>(g1, be1);
    k_conv <<<65536, 256>>>();
    k_gemm2m<<<dim3(8, 1024), 256, GT2_SMEM>>>();
    k_bn2  <<<128, 256>>>(g2, be2);
    k_out  <<<8192, 256>>>(out);
}

// round 12
// speedup vs baseline: 3.1912x; 1.2587x over previous
#include <cuda_runtime.h>
#include <cuda_bf16.h>
#include <cuda_fp16.h>
#include <cstdint>
#include <cstddef>

// ---------------- problem constants ----------------
#define SQ   32
#define PP64 64
#define NB   2048
#define PPRW 4096
#define D1   512
#define D2   1024
#define NKAP 16
#define EPSV 1e-5f

// ---------------- scratch ----------------
__device__ __align__(256) float g_a  [NB * 512];
__device__ __align__(256) float g_hW [NB * 512];
__device__ __align__(256) float g_U  [NB * NKAP * 512];
__device__ __align__(256) float g_V  [NKAP * 512];
__device__ __align__(256) float g_Z1 [(size_t)NB * PP64 * 512];   // 268 MB
__device__ float  g_sum1[SQ * 512];
__device__ float  g_sq1 [SQ * 512];
__device__ float2 g_ab1 [SQ * 512];
__device__ float  g_sum2[SQ * D2];
__device__ float  g_sq2 [SQ * D2];
__device__ float2 g_ab2 [SQ * D2];
__device__ __align__(256) float g_maxZ[NB * D2];
__device__ __align__(256) float g_minZ[NB * D2];
// fp16 operands for HMMA GEMM2 (single-precision-term: A fp16 x B fp16, fp32 accum)
__device__ __align__(256) __half g_Ah[(size_t)NB * PP64 * 512];   // 134 MB
__device__ __align__(256) __half g_Bh[(size_t)D2 * 512];          // W2^T fp16

__device__ __forceinline__ uint32_t smem_u32(const void* p) {
    uint32_t a;
    asm("{ .reg .u64 t; cvta.to.shared.u64 t, %1; cvt.u32.u64 %0, t; }" : "=r"(a) : "l"(p));
    return a;
}

// ---------------- K0: zero BN accumulators ----------------
__global__ void k_zero() {
    int i = blockIdx.x * blockDim.x + threadIdx.x;
    if (i < SQ * 512) { g_sum1[i] = 0.f; g_sq1[i] = 0.f; }
    if (i < SQ * D2)  { g_sum2[i] = 0.f; g_sq2[i] = 0.f; }
}

// ---------------- K1: a = obs @ W_sp ; hW = h @ W1[512:576,:] ----------------
__global__ void k_embed(const float* __restrict__ traj, const float* __restrict__ Wsp,
                        const float* __restrict__ hs,   const float* __restrict__ W1) {
    int b = blockIdx.x;
    int tid = threadIdx.x;
    __shared__ float obs[16];
    __shared__ float hsh[64];
    if (tid < 16) {
        int t = tid >> 1, c = tid & 1;
        obs[tid] = traj[((size_t)t * NB + b) * 2 + c];
    }
    if (tid < 64) hsh[tid] = hs[b * 64 + tid];
    __syncthreads();
#pragma unroll
    for (int q = 0; q < 4; q++) {
        int f = tid + 128 * q;
        float acc = 0.f;
#pragma unroll
        for (int r = 0; r < 16; r++) acc = fmaf(obs[r], Wsp[r * 512 + f], acc);
        g_a[b * 512 + f] = acc;
        float ah = 0.f;
#pragma unroll
        for (int k = 0; k < 64; k++) ah = fmaf(hsh[k], W1[(512 + k) * 512 + f], ah);
        g_hW[b * 512 + f] = ah;
    }
}

// ---------------- K1b: V[kap][d] ----------------
__global__ void k_V(const float* __restrict__ bsp, const float* __restrict__ W1) {
    int d = blockIdx.x * 128 + threadIdx.x;
#pragma unroll
    for (int kap = 0; kap < NKAP; kap++) {
        int par = kap >> 3, t = kap & 7;
        float acc = 0.f;
#pragma unroll 4
        for (int e = par; e < 64; e += 2) {
            int f = t * 64 + e;
            acc = fmaf(bsp[f], W1[f * 512 + d], acc);
        }
        g_V[kap * 512 + d] = acc;
    }
}

// ---------------- K2: U[b][kap][d]; 16 peds/block, kappa split x2 ----------------
__global__ void k_U(const float* __restrict__ W1) {
    int b0 = blockIdx.x * 16;
    int kap0 = blockIdx.y * 8;
    int d  = threadIdx.x;
    __shared__ float a[16][512];
    for (int idx = threadIdx.x; idx < 16 * 512; idx += 512)
        a[idx >> 9][idx & 511] = g_a[b0 * 512 + idx];
    __syncthreads();
#pragma unroll 1
    for (int kk = 0; kk < 8; kk++) {
        int kap = kap0 + kk;
        int par = kap >> 3, t = kap & 7;
        float acc[16];
#pragma unroll
        for (int bb = 0; bb < 16; bb++) acc[bb] = 0.f;
#pragma unroll 8
        for (int e = par; e < 64; e += 2) {
            int f = t * 64 + e;
            float w1 = W1[f * 512 + d];
#pragma unroll
            for (int bb = 0; bb < 16; bb++) acc[bb] = fmaf(a[bb][f], w1, acc[bb]);
        }
#pragma unroll
        for (int bb = 0; bb < 16; bb++)
            g_U[(size_t)((b0 + bb) * NKAP + kap) * 512 + d] = acc[bb];
    }
}

// ---------------- K2b: W2^T -> fp16 ----------------
__global__ void k_wconv(const float* __restrict__ W2) {
    __shared__ float t[32][33];
    int k0 = blockIdx.x * 32, n0 = blockIdx.y * 32;
    int tx = threadIdx.x, ty = threadIdx.y;
#pragma unroll
    for (int r = 0; r < 32; r += 8)
        t[ty + r][tx] = W2[(size_t)(k0 + ty + r) * D2 + n0 + tx];
    __syncthreads();
#pragma unroll
    for (int r = 0; r < 32; r += 8) {
        float v = t[tx][ty + r];
        g_Bh[(size_t)(n0 + ty + r) * 512 + k0 + tx] = __float2half_rn(v);
    }
}

// ---------------- K3a / K3b: Z1 build + BN1 stats ----------------
__global__ void k_p1(const float* __restrict__ tw) {
    int tid = threadIdx.x;
    int dt = blockIdx.x, j = blockIdx.y, s = blockIdx.z;
    int d  = (dt << 7) + tid;
    int bj = (s << 6) + j;
    __shared__ float wsh[64][16];
    for (int idx = tid; idx < 1024; idx += 128) {
        int i = idx >> 4, kap = idx & 15;
        wsh[i][kap] = tw[(size_t)((s << 12) + (i << 6) + j) * 16 + kap];
    }
    float uj[16];
#pragma unroll
    for (int kap = 0; kap < 16; kap++)
        uj[kap] = g_U[(size_t)((bj << 4) + kap) * 512 + d];
    float hwj = g_hW[bj * 512 + d];
    __syncthreads();
    float* zbase = g_Z1 + (size_t)((s << 12) + j) * 512 + d;
#pragma unroll 4
    for (int i = 0; i < 64; i++) {
        float acc = hwj;
#pragma unroll
        for (int kap = 0; kap < 16; kap++) acc = fmaf(wsh[i][kap], uj[kap], acc);
        zbase[(size_t)i * (64 * 512)] = acc;
    }
}

__global__ void k_p2(const float* __restrict__ tw) {
    int tid = threadIdx.x;
    int dt = blockIdx.x, i = blockIdx.y, s = blockIdx.z;
    int d  = (dt << 7) + tid;
    int bi = (s << 6) + i;
    __shared__ float wsh[64][16];
    for (int idx = tid; idx < 1024; idx += 128)
        ((float*)wsh)[idx] = tw[(size_t)((s << 12) + (i << 6)) * 16 + idx];
    float vu[16];
#pragma unroll
    for (int kap = 0; kap < 16; kap++)
        vu[kap] = g_V[(kap << 9) + d] - g_U[(size_t)((bi << 4) + kap) * 512 + d];
    __syncthreads();
    float lsum = 0.f, lsq = 0.f;
    float* zbase = g_Z1 + (size_t)((s << 12) + (i << 6)) * 512 + d;
#pragma unroll 4
    for (int j = 0; j < 64; j++) {
        float acc = 0.f;
#pragma unroll
        for (int kap = 0; kap < 16; kap++) acc = fmaf(wsh[j][kap], vu[kap], acc);
        float z = zbase[(size_t)j * 512] + acc;
        zbase[(size_t)j * 512] = z;
        lsum += z;
        lsq  = fmaf(z, z, lsq);
    }
    atomicAdd(&g_sum1[(s << 9) + d], lsum);
    atomicAdd(&g_sq1 [(s << 9) + d], lsq);
}

// ---------------- K4: finalize BN1 ----------------
__global__ void k_bn1(const float* __restrict__ g1, const float* __restrict__ be1) {
    int idx = blockIdx.x * 256 + threadIdx.x;
    if (idx >= SQ * 512) return;
    int d = idx & 511;
    const float inv = 1.f / (float)PPRW;
    float m   = g_sum1[idx] * inv;
    float var = g_sq1[idx] * inv - m * m;
    float al  = g1[d] * rsqrtf(var + EPSV);
    g_ab1[idx] = make_float2(al, fmaf(-al, m, be1[d]));
}

// ---------------- K4b: A1 = relu(bn1(Z1)) -> fp16 ----------------
__global__ void k_conv() {
    size_t idx = ((size_t)blockIdx.x * 256 + threadIdx.x) * 4;
    float4 z = *(const float4*)(g_Z1 + idx);
    int d = (int)(idx & 511);
    int s = (int)(idx >> 21);
    const float2* abp = g_ab1 + (s << 9) + d;
    float v[4] = {z.x, z.y, z.z, z.w};
    __half hi[4];
#pragma unroll
    for (int q = 0; q < 4; q++) {
        float2 ab = abp[q];
        float a1 = fmaxf(fmaf(ab.x, v[q], ab.y), 0.f);
        hi[q] = __float2half_rn(a1);
    }
    __half2* ph = (__half2*)(g_Ah + idx);
    ph[0] = __halves2half2(hi[0], hi[1]);
    ph[1] = __halves2half2(hi[2], hi[3]);
}

// ---------------- K5: HMMA fp16 GEMM2 (single term) -------------------------
// CTA: M=128 (2 si x 64 j), N=128, K=512 (BK=32). Z2 = A @ B^T, fp32 accum.
#define BK     32
#define APITCH 40                       // fp16 elems per smem row (bank-perm)
#define TILE_B (128 * APITCH * 2)       // 10240 B per operand tile
#define BUF_B  (2 * TILE_B)             // A, B = 20480 B
#define GT2_SMEM (2 * BUF_B)            // 40960 B

__device__ __forceinline__ void mma16816(float* c, const uint32_t* a, const uint32_t* b) {
    asm volatile("mma.sync.aligned.m16n8k16.row.col.f32.f16.f16.f32 "
                 "{%0,%1,%2,%3}, {%4,%5,%6,%7}, {%8,%9}, {%0,%1,%2,%3};"
                 : "+f"(c[0]), "+f"(c[1]), "+f"(c[2]), "+f"(c[3])
                 : "r"(a[0]), "r"(a[1]), "r"(a[2]), "r"(a[3]), "r"(b[0]), "r"(b[1]));
}
#define LDSM_X4(r, addr) \
    asm volatile("ldmatrix.sync.aligned.m8n8.x4.shared.b16 {%0,%1,%2,%3}, [%4];" \
        : "=r"((r)[0]), "=r"((r)[1]), "=r"((r)[2]), "=r"((r)[3]) : "r"(addr))

__global__ void __launch_bounds__(256, 2) k_gemm2m() {
    extern __shared__ __align__(16) char smem[];
    const uint32_t sb = smem_u32(smem);
    const int tid  = threadIdx.x;
    const int wid  = tid >> 5;
    const int lane = tid & 31;
    const int wy   = wid & 3;
    const int wx   = wid >> 2;
    const int g    = lane >> 2;
    const int t    = lane & 3;
    const int nblk = blockIdx.x;
    const int mblk = blockIdx.y;
    const int n0   = nblk << 7;
    const size_t arow0 = (size_t)mblk << 7;
    const int si0  = mblk << 1;

    const int mrow  = ((lane >> 3) & 1) * 8 + (lane & 7);
    const int kselA = (lane >> 4) << 3;
    const int browB = ((lane >> 4) << 3) + (lane & 7);
    const int kselB = ((lane >> 3) & 1) << 3;
    uint32_t offA[2][2], offB[4][2];
#pragma unroll
    for (int mt = 0; mt < 2; mt++)
#pragma unroll
        for (int ks = 0; ks < 2; ks++)
            offA[mt][ks] = (uint32_t)(((wy * 32 + mt * 16 + mrow) * APITCH + ks * 16 + kselA) * 2);
#pragma unroll
    for (int np = 0; np < 4; np++)
#pragma unroll
        for (int ks = 0; ks < 2; ks++)
            offB[np][ks] = (uint32_t)(((wx * 64 + np * 16 + browB) * APITCH + ks * 16 + kselB) * 2);

    float c[2][8][4];
#pragma unroll
    for (int mt = 0; mt < 2; mt++)
#pragma unroll
        for (int nt = 0; nt < 8; nt++)
#pragma unroll
            for (int r = 0; r < 4; r++) c[mt][nt][r] = 0.f;

    // 2 tiles x 512 16B-segments = 1024 = 256 threads x 4
#define ISSUE(c_, buf_) do {                                                   \
    int _k0 = (c_) << 5;                                                       \
    char* _bb = smem + (buf_) * BUF_B;                                         \
    _Pragma("unroll")                                                          \
    for (int _q = 0; _q < 4; _q++) {                                           \
        int _seg = tid + (_q << 8);                                            \
        int _tile = _seg >> 9;                                                 \
        int _r = (_seg >> 2) & 127;                                            \
        int _qq = _seg & 3;                                                    \
        const __half* _src = (_tile == 0)                                      \
            ? g_Ah + ((arow0 + _r) << 9) + _k0 + (_qq << 3)                    \
            : g_Bh + ((size_t)(n0 + _r) << 9) + _k0 + (_qq << 3);              \
        uint32_t _dst;                                                         \
        asm("{ .reg .u64 t; cvta.to.shared.u64 t, %1; cvt.u32.u64 %0, t; }"    \
            : "=r"(_dst) : "l"(_bb + _tile * TILE_B + _r * (APITCH * 2) + (_qq << 4))); \
        asm volatile("cp.async.cg.shared.global [%0], [%1], 16;"               \
                     :: "r"(_dst), "l"(_src));                                 \
    }                                                                          \
    asm volatile("cp.async.commit_group;" ::: "memory");                       \
} while (0)

    ISSUE(0, 0);

    for (int ch = 0; ch < 16; ch++) {
        const int buf = ch & 1;
        if (ch < 15) {
            ISSUE(ch + 1, buf ^ 1);
            asm volatile("cp.async.wait_group 1;" ::: "memory");
        } else {
            asm volatile("cp.async.wait_group 0;" ::: "memory");
        }
        __syncthreads();

        const uint32_t tb = sb + buf * BUF_B;
#pragma unroll
        for (int ks = 0; ks < 2; ks++) {
            uint32_t ax[2][4], bx[8][2];
#pragma unroll
            for (int mt = 0; mt < 2; mt++) LDSM_X4(ax[mt], tb + offA[mt][ks]);
#pragma unroll
            for (int np = 0; np < 4; np++) LDSM_X4(&bx[2 * np][0], tb + TILE_B + offB[np][ks]);
#pragma unroll
            for (int nt = 0; nt < 8; nt++)
#pragma unroll
                for (int mt = 0; mt < 2; mt++) mma16816(c[mt][nt], ax[mt], bx[nt]);
        }
        __syncthreads();
    }
#undef ISSUE

    // ---- epilogue: column-wise max/min/sum/sq over this warp's 32 rows ----
    float* s_mx = (float*)smem;            // [8][64]
    float* s_mn = s_mx + 512;
    float* s_sm = s_mn + 512;
    float* s_sq = s_sm + 512;

#pragma unroll
    for (int nt = 0; nt < 8; nt++) {
#pragma unroll
        for (int b = 0; b < 2; b++) {
            float mx = fmaxf(fmaxf(c[0][nt][b], c[0][nt][b + 2]),
                             fmaxf(c[1][nt][b], c[1][nt][b + 2]));
            float mn = fminf(fminf(c[0][nt][b], c[0][nt][b + 2]),
                             fminf(c[1][nt][b], c[1][nt][b + 2]));
            float sm = c[0][nt][b] + c[0][nt][b + 2] + c[1][nt][b] + c[1][nt][b + 2];
            float sq = c[0][nt][b] * c[0][nt][b] + c[0][nt][b + 2] * c[0][nt][b + 2]
                     + c[1][nt][b] * c[1][nt][b] + c[1][nt][b + 2] * c[1][nt][b + 2];
#pragma unroll
            for (int o = 4; o < 32; o <<= 1) {
                mx = fmaxf(mx, __shfl_xor_sync(0xffffffffu, mx, o));
                mn = fminf(mn, __shfl_xor_sync(0xffffffffu, mn, o));
                sm += __shfl_xor_sync(0xffffffffu, sm, o);
                sq += __shfl_xor_sync(0xffffffffu, sq, o);
            }
            if (g == 0) {
                int cl = wid * 64 + (nt << 3) + 2 * t + b;
                s_mx[cl] = mx; s_mn[cl] = mn; s_sm[cl] = sm; s_sq[cl] = sq;
            }
        }
    }
    __syncthreads();

    {
        int jg = tid >> 7, col = tid & 127;
        int wxx = col >> 6, c64 = col & 63;
        int w0 = (wxx << 2) + (jg << 1);
        float mx = fmaxf(s_mx[w0 * 64 + c64], s_mx[(w0 + 1) * 64 + c64]);
        float mn = fminf(s_mn[w0 * 64 + c64], s_mn[(w0 + 1) * 64 + c64]);
        int si = si0 + jg;
        g_maxZ[(size_t)si * D2 + n0 + col] = mx;
        g_minZ[(size_t)si * D2 + n0 + col] = mn;
    }
    if (tid < 128) {
        int col = tid, wxx = col >> 6, c64 = col & 63;
        float sm = 0.f, sq = 0.f;
#pragma unroll
        for (int w = 0; w < 4; w++) {
            sm += s_sm[((wxx << 2) + w) * 64 + c64];
            sq += s_sq[((wxx << 2) + w) * 64 + c64];
        }
        int s_ = si0 >> 6;
        atomicAdd(&g_sum2[s_ * D2 + n0 + col], sm);
        atomicAdd(&g_sq2 [s_ * D2 + n0 + col], sq);
    }
}

// ---------------- K6: finalize BN2 ----------------
__global__ void k_bn2(const float* __restrict__ g2, const float* __restrict__ be2) {
    int idx = blockIdx.x * 256 + threadIdx.x;
    if (idx >= SQ * D2) return;
    int d = idx & (D2 - 1);
    const float inv = 1.f / (float)PPRW;
    float m   = g_sum2[idx] * inv;
    float var = g_sq2[idx] * inv - m * m;
    float al  = g2[d] * rsqrtf(var + EPSV);
    g_ab2[idx] = make_float2(al, fmaf(-al, m, be2[d]));
}

// ---------------- K7: out ----------------
__global__ void k_out(float* __restrict__ out) {
    int idx = blockIdx.x * 256 + threadIdx.x;
    int si = idx >> 10;
    int d  = idx & (D2 - 1);
    int s  = si >> 6;
    float2 abv = g_ab2[s * D2 + d];
    float m = (abv.x >= 0.f) ? g_maxZ[idx] : g_minZ[idx];
    out[idx] = fmaxf(fmaf(abv.x, m, abv.y), 0.f);
}

// ---------------- launch ----------------
extern "C" void kernel_launch(void* const* d_in, const int* in_sizes, int n_in,
                              void* d_out, int out_size) {
    (void)in_sizes; (void)n_in; (void)out_size;
    const float* hs   = (const float*)d_in[0];
    const float* traj = (const float*)d_in[3];
    const float* tw   = (const float*)d_in[4];
    const float* Wsp  = (const float*)d_in[6];
    const float* bsp  = (const float*)d_in[7];
    const float* W1   = (const float*)d_in[8];
    const float* g1   = (const float*)d_in[10];
    const float* be1  = (const float*)d_in[11];
    const float* W2   = (const float*)d_in[12];
    const float* g2   = (const float*)d_in[14];
    const float* be2  = (const float*)d_in[15];
    float* out = (float*)d_out;

    cudaFuncSetAttribute(k_gemm2m, cudaFuncAttributeMaxDynamicSharedMemorySize, GT2_SMEM);

    k_zero <<<128, 256>>>();
    k_embed<<<NB, 128>>>(traj, Wsp, hs, W1);
    k_V    <<<4, 128>>>(bsp, W1);
    k_U    <<<dim3(NB / 16, 2), 512>>>(W1);
    k_wconv<<<dim3(16, 32), dim3(32, 8)>>>(W2);
    k_p1   <<<dim3(4, 64, SQ), 128>>>(tw);
    k_p2   <<<dim3(4, 64, SQ), 128>>>(tw);
    k_bn1  <<<64, 256>>>(g1, be1);
    k_conv <<<65536, 256>>>();
    k_gemm2m<<<dim3(8, 1024), 256, GT2_SMEM>>>();
    k_bn2  <<<128, 256>>>(g2, be2);
    k_out  <<<8192, 256>>>(out);
}